// round 3
// baseline (speedup 1.0000x reference)
#include <cuda_runtime.h>
#include <mma.h>
#include <math.h>
#include <stdint.h>

using namespace nvcuda;

// Problem constants
#define Bc     16
#define L1c    512
#define L2c    512
#define Dc     512
#define Hc     8
#define INNERc 1024
#define HDc    128
#define DCc    640   // D + HD

// ---------------- scratch (static device globals; no allocation) -------------
__device__ float g_T  [(size_t)Bc*Hc*L1c*Dc];
__device__ float g_aff[(size_t)Bc*Hc*L1c*L2c];
__device__ float g_PP [(size_t)Bc*L1c*INNERc];
__device__ float g_PS [(size_t)Bc*L2c*INNERc];
__device__ float g_wp [(size_t)Bc*Hc*L2c*HDc];
__device__ float g_ws [(size_t)Bc*Hc*L1c*HDc];
__device__ float g_poolp[(size_t)Bc*L2c*HDc];
__device__ float g_pools[(size_t)Bc*L1c*HDc];
__device__ float g_catp[(size_t)Bc*L1c*DCc];
__device__ float g_cats[(size_t)Bc*L2c*DCc];

// ---------------- helpers -----------------------------------------------------
__device__ __forceinline__ uint32_t smem_u32(const void* p) {
    uint32_t a;
    asm("{ .reg .u64 t; cvta.to.shared.u64 t, %1; cvt.u32.u64 %0, t; }" : "=r"(a) : "l"(p));
    return a;
}
__device__ __forceinline__ float tf32r(float x) {   // round-to-nearest tf32
    uint32_t u;
    asm("cvt.rna.tf32.f32 %0, %1;" : "=r"(u) : "f"(x));
    return __uint_as_float(u);
}
__device__ __forceinline__ void cpa16(uint32_t dst, const float* src) {
    asm volatile("cp.async.cg.shared.global [%0], [%1], 16;" :: "r"(dst), "l"(src));
}
__device__ __forceinline__ void cpa4(uint32_t dst, const float* src) {
    asm volatile("cp.async.ca.shared.global [%0], [%1], 4;" :: "r"(dst), "l"(src));
}
__device__ __forceinline__ void cpa_commit() {
    asm volatile("cp.async.commit_group;" ::: "memory");
}
__device__ __forceinline__ void cpa_wait1() {
    asm volatile("cp.async.wait_group 1;" ::: "memory");
}
__device__ __forceinline__ void cpa_wait0() {
    asm volatile("cp.async.wait_group 0;" ::: "memory");
}

// Tile geometry: 128 rows x 32 k, row stride 40 floats (160B, 32B aligned,
// conflict-benign). One tile = 128*40 = 5120 floats = 20480 B.
#define TLD    40
#define TFLT   5120

// stage a 128x32 tile.
// TR=false: source G[(rb+r)*ld + k0+k]  (rows of the tile are contiguous in K)
// TR=true : source G[(k0+k)*ld + rb+r]  (transpose while staging, 4B cp.async)
template<bool TR>
__device__ __forceinline__ void stage(const float* __restrict__ G, int ld,
                                      int rb, int k0, uint32_t dstb) {
    const int tid = threadIdx.x;
    if (!TR) {
        #pragma unroll
        for (int r = 0; r < 4; r++) {
            int idx = r * 256 + tid;
            int m  = idx >> 3;
            int kq = (idx & 7) << 2;
            cpa16(dstb + m * 160 + kq * 4, G + (size_t)(rb + m) * ld + k0 + kq);
        }
    } else {
        #pragma unroll
        for (int r = 0; r < 16; r++) {
            int idx = r * 256 + tid;
            int n  = idx & 127;
            int kk = idx >> 7;
            cpa4(dstb + n * 160 + kk * 4, G + (size_t)(k0 + kk) * ld + rb + n);
        }
    }
}

typedef wmma::fragment<wmma::matrix_a, 16, 16, 8, wmma::precision::tf32, wmma::row_major> FragA;
typedef wmma::fragment<wmma::matrix_b, 16, 16, 8, wmma::precision::tf32, wmma::col_major> FragB;
typedef wmma::fragment<wmma::accumulator, 16, 16, 8, float> FragC;

// ---------------- core GEMM ---------------------------------------------------
// C[128x128 tile] = A(MxK) * B(KxN), tf32 3-pass split (fp32-grade accuracy).
// As[m][k], Bs[n][k] both staged as 128x32 row-major-in-k tiles.
// EPI: 0 plain, 1 tanh*rs[row]*cs[col], 2 relu, 3 relu(+bias[col])
template<bool TRA, bool TRB, int EPI>
__device__ __forceinline__ void gemm_core(
    const float* __restrict__ A, const float* __restrict__ B, float* __restrict__ C,
    int K, int lda, int ldb, int ldc,
    const float* __restrict__ rs, const float* __restrict__ cs,
    const float* __restrict__ bias)
{
    extern __shared__ float sm[];
    const uint32_t smb = smem_u32(sm);

    const int tid  = threadIdx.x;
    const int wid  = tid >> 5;
    const int lane = tid & 31;
    const int wm   = wid & 3;        // warp row   (4)
    const int wn   = wid >> 2;       // warp col   (2)
    const int row0 = blockIdx.y * 128;
    const int col0 = blockIdx.x * 128;

    FragC acc[2][4];
    #pragma unroll
    for (int i = 0; i < 2; i++)
        #pragma unroll
        for (int j = 0; j < 4; j++) wmma::fill_fragment(acc[i][j], 0.0f);

    const int NCH = K >> 5;

    // prologue: stage chunk 0 into buffer 0
    stage<TRA>(A, lda, row0, 0, smb);
    stage<TRB>(B, ldb, col0, 0, smb + TFLT * 4);
    cpa_commit();

    for (int c = 0; c < NCH; c++) {
        if (c + 1 < NCH) {
            uint32_t nb = smb + ((c + 1) & 1) * 2u * TFLT * 4u;
            stage<TRA>(A, lda, row0, (c + 1) << 5, nb);
            stage<TRB>(B, ldb, col0, (c + 1) << 5, nb + TFLT * 4);
            cpa_commit();
            cpa_wait1();
        } else {
            cpa_wait0();
        }
        __syncthreads();

        const float* As = sm + (c & 1) * 2 * TFLT;
        const float* Bs = As + TFLT;

        #pragma unroll
        for (int ks = 0; ks < 4; ks++) {
            FragA a_raw[2], a_hi[2];
            FragB b_raw[4], b_hi[4];
            #pragma unroll
            for (int ti = 0; ti < 2; ti++)
                wmma::load_matrix_sync(a_raw[ti],
                    As + (wm * 32 + ti * 16) * TLD + ks * 8, TLD);
            #pragma unroll
            for (int tj = 0; tj < 4; tj++)
                wmma::load_matrix_sync(b_raw[tj],
                    Bs + (wn * 64 + tj * 16) * TLD + ks * 8, TLD);

            // hi parts
            #pragma unroll
            for (int ti = 0; ti < 2; ti++)
                #pragma unroll
                for (int e = 0; e < a_hi[ti].num_elements; e++)
                    a_hi[ti].x[e] = tf32r(a_raw[ti].x[e]);
            #pragma unroll
            for (int tj = 0; tj < 4; tj++)
                #pragma unroll
                for (int e = 0; e < b_hi[tj].num_elements; e++)
                    b_hi[tj].x[e] = tf32r(b_raw[tj].x[e]);

            // pass 1: Ah * Bh
            #pragma unroll
            for (int ti = 0; ti < 2; ti++)
                #pragma unroll
                for (int tj = 0; tj < 4; tj++)
                    wmma::mma_sync(acc[ti][tj], a_hi[ti], b_hi[tj], acc[ti][tj]);

            // a_lo (reuse a_raw storage)
            #pragma unroll
            for (int ti = 0; ti < 2; ti++)
                #pragma unroll
                for (int e = 0; e < a_raw[ti].num_elements; e++)
                    a_raw[ti].x[e] = tf32r(a_raw[ti].x[e] - a_hi[ti].x[e]);
            // pass 2: Al * Bh
            #pragma unroll
            for (int ti = 0; ti < 2; ti++)
                #pragma unroll
                for (int tj = 0; tj < 4; tj++)
                    wmma::mma_sync(acc[ti][tj], a_raw[ti], b_hi[tj], acc[ti][tj]);

            // b_lo (reuse b_raw storage)
            #pragma unroll
            for (int tj = 0; tj < 4; tj++)
                #pragma unroll
                for (int e = 0; e < b_raw[tj].num_elements; e++)
                    b_raw[tj].x[e] = tf32r(b_raw[tj].x[e] - b_hi[tj].x[e]);
            // pass 3: Ah * Bl
            #pragma unroll
            for (int ti = 0; ti < 2; ti++)
                #pragma unroll
                for (int tj = 0; tj < 4; tj++)
                    wmma::mma_sync(acc[ti][tj], a_hi[ti], b_raw[tj], acc[ti][tj]);
        }
        __syncthreads();   // protect buffer before it is restaged
    }

    // ---------------- epilogue via smem C buffer (reuses tile smem) ----------
    float* Cs = sm;        // 128 x 136 floats = 69632 B <= 81920 B
    #pragma unroll
    for (int ti = 0; ti < 2; ti++)
        #pragma unroll
        for (int tj = 0; tj < 4; tj++)
            wmma::store_matrix_sync(Cs + (wm * 32 + ti * 16) * 136 + wn * 64 + tj * 16,
                                    acc[ti][tj], 136, wmma::mem_row_major);
    __syncthreads();

    #pragma unroll
    for (int it = 0; it < 16; it++) {
        int row = it * 8 + wid;
        float4 v = *(float4*)(Cs + row * 136 + lane * 4);
        if (EPI == 1) {
            float rm = rs[row0 + row];
            v.x = tanhf(v.x) * rm * cs[col0 + lane * 4 + 0];
            v.y = tanhf(v.y) * rm * cs[col0 + lane * 4 + 1];
            v.z = tanhf(v.z) * rm * cs[col0 + lane * 4 + 2];
            v.w = tanhf(v.w) * rm * cs[col0 + lane * 4 + 3];
        } else if (EPI == 2) {
            v.x = fmaxf(v.x, 0.f); v.y = fmaxf(v.y, 0.f);
            v.z = fmaxf(v.z, 0.f); v.w = fmaxf(v.w, 0.f);
        } else if (EPI == 3) {
            v.x = fmaxf(v.x + bias[col0 + lane * 4 + 0], 0.f);
            v.y = fmaxf(v.y + bias[col0 + lane * 4 + 1], 0.f);
            v.z = fmaxf(v.z + bias[col0 + lane * 4 + 2], 0.f);
            v.w = fmaxf(v.w + bias[col0 + lane * 4 + 3], 0.f);
        }
        *(float4*)(C + (size_t)(row0 + row) * ldc + col0 + lane * 4) = v;
    }
}

// ---------------- stage wrappers ----------------------------------------------
// A layouts: [M,K] direct (TRA=0) or [K,M] (TRA=1). B: [N,K] direct or [K,N] TR.

__global__ __launch_bounds__(256) void k_pw(const float* __restrict__ P,
                                            const float* __restrict__ Waff) {
    int bh = blockIdx.z;
    gemm_core<false, true, 0>(P + (size_t)(bh >> 3) * L1c * Dc,
                              Waff + (size_t)(bh & 7) * Dc * Dc,          // [K=e][N=f]
                              g_T + (size_t)bh * L1c * Dc,
                              Dc, Dc, Dc, Dc, nullptr, nullptr, nullptr);
}
__global__ __launch_bounds__(256) void k_aff(const float* __restrict__ S,
                                             const float* __restrict__ pm,
                                             const float* __restrict__ sm_) {
    int bh = blockIdx.z, b = bh >> 3;
    gemm_core<false, false, 1>(g_T + (size_t)bh * L1c * Dc,
                               S + (size_t)b * L2c * Dc,                  // [N=j][K=f]
                               g_aff + (size_t)bh * L1c * L2c,
                               Dc, Dc, Dc, L2c,
                               pm + b * L1c, sm_ + b * L2c, nullptr);
}
__global__ __launch_bounds__(256) void k_projP(const float* __restrict__ X,
                                               const float* __restrict__ W) {
    int b = blockIdx.z;
    gemm_core<false, true, 0>(X + (size_t)b * L1c * Dc, W,                // [K=e][N=u]
                              g_PP + (size_t)b * L1c * INNERc,
                              Dc, Dc, INNERc, INNERc, nullptr, nullptr, nullptr);
}
__global__ __launch_bounds__(256) void k_projS(const float* __restrict__ X,
                                               const float* __restrict__ W) {
    int b = blockIdx.z;
    gemm_core<false, true, 0>(X + (size_t)b * L2c * Dc, W,
                              g_PS + (size_t)b * L2c * INNERc,
                              Dc, Dc, INNERc, INNERc, nullptr, nullptr, nullptr);
}
// wp[j,d] = relu( sum_i aff[i,j] * pp[i,d] ):  A=aff [K=i][M=j], B=pp [K=i][N=d]
__global__ __launch_bounds__(256) void k_wp() {
    int bh = blockIdx.z, b = bh >> 3, h = bh & 7;
    gemm_core<true, true, 2>(g_aff + (size_t)bh * L1c * L2c,
                             g_PP + (size_t)b * L1c * INNERc + h * HDc,
                             g_wp + (size_t)bh * L2c * HDc,
                             L1c, L2c, INNERc, HDc, nullptr, nullptr, nullptr);
}
// ws[i,d] = relu( sum_j aff[i,j] * ps[j,d] ):  A=aff [M=i][K=j], B=ps [K=j][N=d]
__global__ __launch_bounds__(256) void k_ws() {
    int bh = blockIdx.z, b = bh >> 3, h = bh & 7;
    gemm_core<false, true, 2>(g_aff + (size_t)bh * L1c * L2c,
                              g_PS + (size_t)b * L2c * INNERc + h * HDc,
                              g_ws + (size_t)bh * L1c * HDc,
                              L2c, L2c, INNERc, HDc, nullptr, nullptr, nullptr);
}
__global__ __launch_bounds__(256) void k_ffnp(const float* __restrict__ W,
                                              const float* __restrict__ bias,
                                              float* __restrict__ O) {
    int b = blockIdx.z;
    gemm_core<false, true, 3>(g_catp + (size_t)b * L1c * DCc, W,          // [K=c][N=o]
                              O + (size_t)b * L1c * Dc,
                              DCc, DCc, Dc, Dc, nullptr, nullptr, bias);
}
__global__ __launch_bounds__(256) void k_ffns(const float* __restrict__ W,
                                              const float* __restrict__ bias,
                                              float* __restrict__ O) {
    int b = blockIdx.z;
    gemm_core<false, true, 3>(g_cats + (size_t)b * L2c * DCc, W,
                              O + (size_t)b * L2c * Dc,
                              DCc, DCc, Dc, Dc, nullptr, nullptr, bias);
}

// ---------------- elementwise stages ------------------------------------------
__global__ void k_poolp() {
    int idx = blockIdx.x * blockDim.x + threadIdx.x;
    const int tot = Bc * L2c * HDc;
    if (idx >= tot) return;
    int b = idx / (L2c * HDc);
    int r = idx - b * (L2c * HDc);
    float m = g_wp[((size_t)b * Hc) * L2c * HDc + r];
    #pragma unroll
    for (int h = 1; h < Hc; h++)
        m = fmaxf(m, g_wp[((size_t)(b * Hc + h)) * L2c * HDc + r]);
    g_poolp[idx] = m;
}
__global__ void k_pools() {
    int idx = blockIdx.x * blockDim.x + threadIdx.x;
    const int tot = Bc * L1c * HDc;
    if (idx >= tot) return;
    int b = idx / (L1c * HDc);
    int r = idx - b * (L1c * HDc);
    float m = g_ws[((size_t)b * Hc) * L1c * HDc + r];
    #pragma unroll
    for (int h = 1; h < Hc; h++)
        m = fmaxf(m, g_ws[((size_t)(b * Hc + h)) * L1c * HDc + r]);
    g_pools[idx] = m;
}
__global__ void k_catp(const float* __restrict__ P) {
    int idx = blockIdx.x * blockDim.x + threadIdx.x;
    const int tot = Bc * L1c * DCc;
    if (idx >= tot) return;
    int bi = idx / DCc;
    int c  = idx - bi * DCc;
    g_catp[idx] = (c < Dc) ? P[(size_t)bi * Dc + c]
                           : g_pools[(size_t)bi * HDc + (c - Dc)];
}
__global__ void k_cats(const float* __restrict__ S) {
    int idx = blockIdx.x * blockDim.x + threadIdx.x;
    const int tot = Bc * L2c * DCc;
    if (idx >= tot) return;
    int bi = idx / DCc;
    int c  = idx - bi * DCc;
    g_cats[idx] = (c < Dc) ? S[(size_t)bi * Dc + c]
                           : g_poolp[(size_t)bi * HDc + (c - Dc)];
}

// ---------------- launcher ----------------------------------------------------
extern "C" void kernel_launch(void* const* d_in, const int* in_sizes, int n_in,
                              void* d_out, int out_size) {
    const float* P    = (const float*)d_in[0];
    const float* S    = (const float*)d_in[1];
    const float* pm   = (const float*)d_in[2];
    const float* sm   = (const float*)d_in[3];
    const float* Waff = (const float*)d_in[4];
    const float* Wp   = (const float*)d_in[5];
    const float* Ws   = (const float*)d_in[6];
    const float* Wfp  = (const float*)d_in[7];
    const float* bfp  = (const float*)d_in[8];
    const float* Wfs  = (const float*)d_in[9];
    const float* bfs  = (const float*)d_in[10];

    float* outp = (float*)d_out;
    float* outs = outp + (size_t)Bc * L1c * Dc;

    const int SMEM = 4 * TFLT * 4;   // 81920 B (double-buffered A+B tiles; C reuses)

    static int inited = 0;
    if (!inited) {
        cudaFuncSetAttribute(k_pw,    cudaFuncAttributeMaxDynamicSharedMemorySize, SMEM);
        cudaFuncSetAttribute(k_aff,   cudaFuncAttributeMaxDynamicSharedMemorySize, SMEM);
        cudaFuncSetAttribute(k_projP, cudaFuncAttributeMaxDynamicSharedMemorySize, SMEM);
        cudaFuncSetAttribute(k_projS, cudaFuncAttributeMaxDynamicSharedMemorySize, SMEM);
        cudaFuncSetAttribute(k_wp,    cudaFuncAttributeMaxDynamicSharedMemorySize, SMEM);
        cudaFuncSetAttribute(k_ws,    cudaFuncAttributeMaxDynamicSharedMemorySize, SMEM);
        cudaFuncSetAttribute(k_ffnp,  cudaFuncAttributeMaxDynamicSharedMemorySize, SMEM);
        cudaFuncSetAttribute(k_ffns,  cudaFuncAttributeMaxDynamicSharedMemorySize, SMEM);
        inited = 1;
    }

    dim3 blk(256);

    k_pw   <<<dim3(4, 4, Bc * Hc), blk, SMEM>>>(P, Waff);
    k_aff  <<<dim3(4, 4, Bc * Hc), blk, SMEM>>>(S, pm, sm);
    k_projP<<<dim3(8, 4, Bc),      blk, SMEM>>>(P, Wp);
    k_projS<<<dim3(8, 4, Bc),      blk, SMEM>>>(S, Ws);
    k_wp   <<<dim3(1, 4, Bc * Hc), blk, SMEM>>>();
    k_ws   <<<dim3(1, 4, Bc * Hc), blk, SMEM>>>();

    { int tot = Bc * L2c * HDc; k_poolp<<<(tot + 255) / 256, 256>>>(); }
    { int tot = Bc * L1c * HDc; k_pools<<<(tot + 255) / 256, 256>>>(); }
    { int tot = Bc * L1c * DCc; k_catp<<<(tot + 255) / 256, 256>>>(P); }
    { int tot = Bc * L2c * DCc; k_cats<<<(tot + 255) / 256, 256>>>(S); }

    k_ffnp <<<dim3(4, 4, Bc), blk, SMEM>>>(Wfp, bfp, outp);
    k_ffns <<<dim3(4, 4, Bc), blk, SMEM>>>(Wfs, bfs, outs);
}

// round 4
// speedup vs baseline: 2.3258x; 2.3258x over previous
#include <cuda_runtime.h>
#include <cuda_fp16.h>
#include <mma.h>
#include <math.h>
#include <stdint.h>

using namespace nvcuda;

// Problem constants
#define Bc     16
#define L1c    512
#define L2c    512
#define Dc     512
#define Hc     8
#define INNERc 1024
#define HDc    128
#define DCc    640   // D + HD

// ---------------- scratch (static device globals; no allocation) -------------
__device__ float g_T  [(size_t)Bc*Hc*L1c*Dc];
__device__ float g_aff[(size_t)Bc*Hc*L1c*L2c];
__device__ float g_PP [(size_t)Bc*L1c*INNERc];
__device__ float g_PS [(size_t)Bc*L2c*INNERc];
__device__ float g_wp [(size_t)Bc*Hc*L2c*HDc];
__device__ float g_ws [(size_t)Bc*Hc*L1c*HDc];
__device__ float g_poolp[(size_t)Bc*L2c*HDc];
__device__ float g_pools[(size_t)Bc*L1c*HDc];

// ---------------- helpers -----------------------------------------------------
__device__ __forceinline__ uint32_t smem_u32(const void* p) {
    uint32_t a;
    asm("{ .reg .u64 t; cvta.to.shared.u64 t, %1; cvt.u32.u64 %0, t; }" : "=r"(a) : "l"(p));
    return a;
}
__device__ __forceinline__ void cpa16(uint32_t dst, const float* src) {
    asm volatile("cp.async.cg.shared.global [%0], [%1], 16;" :: "r"(dst), "l"(src));
}
__device__ __forceinline__ void cpa4(uint32_t dst, const float* src) {
    asm volatile("cp.async.ca.shared.global [%0], [%1], 4;" :: "r"(dst), "l"(src));
}
__device__ __forceinline__ void cpa_commit() { asm volatile("cp.async.commit_group;" ::: "memory"); }
__device__ __forceinline__ void cpa_wait1()  { asm volatile("cp.async.wait_group 1;" ::: "memory"); }
__device__ __forceinline__ void cpa_wait0()  { asm volatile("cp.async.wait_group 0;" ::: "memory"); }

// f32 staging tile: 128 rows x 32 k, row stride 40 floats (160 B).
#define TLD32  40
#define TF32   5120                 // floats per f32 tile
#define TF32B  (TF32 * 4)           // 20480 B
// fp16 tile: 128 rows x 32 k halves, row stride 40 halves (80 B).
#define TLD16  40
#define TH16B  (128 * 40 * 2)       // 10240 B

// smem map (bytes):
//   [0,  81920)  f32 tiles: buf0{A,B}, buf1{A,B}
//   [81920, 122880) fp16 tiles: Ah, Al, Bh, Bl
#define OFF_F16  81920
#define SMEM_TOT 122880

// ---- staging (global f32 -> smem f32 via cp.async) ---------------------------
// AMODE 0: G[(rb+r)*ld + k0+k]   row-major rows
// AMODE 1: G[(k0+k)*ld + rb+r]   transpose while staging
// AMODE 2: concat: k<512 -> X[(rb+r)*512 + k], else pool[(rb+r)*128 + k-512]
template<int AMODE>
__device__ __forceinline__ void stage(const float* __restrict__ G, int ld,
                                      const float* __restrict__ pool,
                                      int rb, int k0, uint32_t dstb) {
    const int tid = threadIdx.x;
    if (AMODE == 0) {
        #pragma unroll
        for (int r = 0; r < 4; r++) {
            int idx = r * 256 + tid;
            int m  = idx >> 3;
            int kq = (idx & 7) << 2;
            cpa16(dstb + m * 160 + kq * 4, G + (size_t)(rb + m) * ld + k0 + kq);
        }
    } else if (AMODE == 1) {
        #pragma unroll
        for (int r = 0; r < 16; r++) {
            int idx = r * 256 + tid;
            int n  = idx & 127;
            int kk = idx >> 7;
            cpa4(dstb + n * 160 + kk * 4, G + (size_t)(k0 + kk) * ld + rb + n);
        }
    } else {
        #pragma unroll
        for (int r = 0; r < 4; r++) {
            int idx = r * 256 + tid;
            int m  = idx >> 3;
            int kq = (idx & 7) << 2;
            int gk = k0 + kq;
            const float* src = (gk < Dc)
                ? G    + (size_t)(rb + m) * Dc  + gk
                : pool + (size_t)(rb + m) * HDc + (gk - Dc);
            cpa16(dstb + m * 160 + kq * 4, src);
        }
    }
}

// ---- convert f32 tile -> pre-split fp16 hi/lo tiles --------------------------
__device__ __forceinline__ void convert_tile(const float* __restrict__ F,
                                             __half* __restrict__ Hh,
                                             __half* __restrict__ Hl) {
    const int tid = threadIdx.x;
    #pragma unroll
    for (int r = 0; r < 4; r++) {
        int idx = r * 256 + tid;
        int m  = idx >> 3;
        int kq = (idx & 7) << 2;
        float4 v = *(const float4*)(F + m * TLD32 + kq);
        __half hx = __float2half_rn(v.x), hy = __float2half_rn(v.y);
        __half hz = __float2half_rn(v.z), hw = __float2half_rn(v.w);
        __half lx = __float2half_rn(v.x - __half2float(hx));
        __half ly = __float2half_rn(v.y - __half2float(hy));
        __half lz = __float2half_rn(v.z - __half2float(hz));
        __half lw = __float2half_rn(v.w - __half2float(hw));
        __half2* ph = (__half2*)(Hh + m * TLD16 + kq);
        __half2* pl = (__half2*)(Hl + m * TLD16 + kq);
        ph[0] = __halves2half2(hx, hy); ph[1] = __halves2half2(hz, hw);
        pl[0] = __halves2half2(lx, ly); pl[1] = __halves2half2(lz, lw);
    }
}

typedef wmma::fragment<wmma::matrix_a, 16, 16, 16, __half, wmma::row_major> FragA;
typedef wmma::fragment<wmma::matrix_b, 16, 16, 16, __half, wmma::col_major> FragB;
typedef wmma::fragment<wmma::accumulator, 16, 16, 16, float> FragC;

// ---------------- core GEMM ---------------------------------------------------
// C(128x128 tile) = A(MxK) x B(KxN); fp16 3-pass split, fp32-grade.
// EPI: 0 plain direct-store, 1 tanh*rs*cs (smem), 2 relu direct-store,
//      3 relu(+bias) (smem)
template<int AMODE, int BMODE, int EPI>
__device__ __forceinline__ void gemm_core(
    const float* __restrict__ A, const float* __restrict__ B, float* __restrict__ C,
    int K, int lda, int ldb, int ldc,
    const float* __restrict__ apool,
    const float* __restrict__ rs, const float* __restrict__ cs,
    const float* __restrict__ bias)
{
    extern __shared__ float sm[];
    const uint32_t smb = smem_u32(sm);
    __half* Ah = (__half*)((char*)sm + OFF_F16);
    __half* Al = (__half*)((char*)sm + OFF_F16 + TH16B);
    __half* Bh = (__half*)((char*)sm + OFF_F16 + 2 * TH16B);
    __half* Bl = (__half*)((char*)sm + OFF_F16 + 3 * TH16B);

    const int tid  = threadIdx.x;
    const int wid  = tid >> 5;
    const int lane = tid & 31;
    const int wm   = wid & 3;        // warp row (4)
    const int wn   = wid >> 2;       // warp col (2)
    const int row0 = blockIdx.y * 128;
    const int col0 = blockIdx.x * 128;

    FragC acc[2][4];
    #pragma unroll
    for (int i = 0; i < 2; i++)
        #pragma unroll
        for (int j = 0; j < 4; j++) wmma::fill_fragment(acc[i][j], 0.0f);

    const int NCH = K >> 5;

    stage<AMODE>(A, lda, apool, row0, 0, smb);
    stage<BMODE>(B, ldb, nullptr, col0, 0, smb + TF32B);
    cpa_commit();

    for (int c = 0; c < NCH; c++) {
        if (c + 1 < NCH) {
            uint32_t nb = smb + ((c + 1) & 1) * 2u * TF32B;
            stage<AMODE>(A, lda, apool, row0, (c + 1) << 5, nb);
            stage<BMODE>(B, ldb, nullptr, col0, (c + 1) << 5, nb + TF32B);
            cpa_commit();
            cpa_wait1();
        } else {
            cpa_wait0();
        }
        __syncthreads();   // f32 buf ready; previous chunk's mma done (fp16 tiles free)

        const float* Fa = sm + (c & 1) * 2 * TF32;
        const float* Fb = Fa + TF32;
        convert_tile(Fa, Ah, Al);
        convert_tile(Fb, Bh, Bl);
        __syncthreads();

        #pragma unroll
        for (int ks = 0; ks < 2; ks++) {
            FragA fah[2], fal[2];
            #pragma unroll
            for (int ti = 0; ti < 2; ti++) {
                int ro = (wm * 32 + ti * 16) * TLD16 + ks * 16;
                wmma::load_matrix_sync(fah[ti], Ah + ro, TLD16);
                wmma::load_matrix_sync(fal[ti], Al + ro, TLD16);
            }
            #pragma unroll
            for (int tj = 0; tj < 4; tj++) {
                FragB fbh, fbl;
                int co = (wn * 64 + tj * 16) * TLD16 + ks * 16;
                wmma::load_matrix_sync(fbh, Bh + co, TLD16);
                wmma::load_matrix_sync(fbl, Bl + co, TLD16);
                #pragma unroll
                for (int ti = 0; ti < 2; ti++) {
                    wmma::mma_sync(acc[ti][tj], fah[ti], fbh, acc[ti][tj]);
                    wmma::mma_sync(acc[ti][tj], fal[ti], fbh, acc[ti][tj]);
                    wmma::mma_sync(acc[ti][tj], fah[ti], fbl, acc[ti][tj]);
                }
            }
        }
        // no trailing sync: next iteration's post-wait sync is the barrier
    }

    if (EPI == 0 || EPI == 2) {
        // direct fragment stores (relu is elementwise-safe on opaque frags)
        #pragma unroll
        for (int ti = 0; ti < 2; ti++)
            #pragma unroll
            for (int tj = 0; tj < 4; tj++) {
                if (EPI == 2) {
                    #pragma unroll
                    for (int e = 0; e < acc[ti][tj].num_elements; e++)
                        acc[ti][tj].x[e] = fmaxf(acc[ti][tj].x[e], 0.f);
                }
                wmma::store_matrix_sync(
                    C + (size_t)(row0 + wm * 32 + ti * 16) * ldc + col0 + wn * 64 + tj * 16,
                    acc[ti][tj], ldc, wmma::mem_row_major);
            }
        return;
    }

    // smem epilogue (needs row/col indices)
    __syncthreads();
    float* Cs = sm;   // 128 x 136 floats = 69632 B
    #pragma unroll
    for (int ti = 0; ti < 2; ti++)
        #pragma unroll
        for (int tj = 0; tj < 4; tj++)
            wmma::store_matrix_sync(Cs + (wm * 32 + ti * 16) * 136 + wn * 64 + tj * 16,
                                    acc[ti][tj], 136, wmma::mem_row_major);
    __syncthreads();

    #pragma unroll
    for (int it = 0; it < 16; it++) {
        int row = it * 8 + wid;
        float4 v = *(float4*)(Cs + row * 136 + lane * 4);
        if (EPI == 1) {
            float rm = rs[row0 + row];
            v.x = tanhf(v.x) * rm * cs[col0 + lane * 4 + 0];
            v.y = tanhf(v.y) * rm * cs[col0 + lane * 4 + 1];
            v.z = tanhf(v.z) * rm * cs[col0 + lane * 4 + 2];
            v.w = tanhf(v.w) * rm * cs[col0 + lane * 4 + 3];
        } else {   // EPI == 3
            v.x = fmaxf(v.x + bias[col0 + lane * 4 + 0], 0.f);
            v.y = fmaxf(v.y + bias[col0 + lane * 4 + 1], 0.f);
            v.z = fmaxf(v.z + bias[col0 + lane * 4 + 2], 0.f);
            v.w = fmaxf(v.w + bias[col0 + lane * 4 + 3], 0.f);
        }
        *(float4*)(C + (size_t)(row0 + row) * ldc + col0 + lane * 4) = v;
    }
}

// ---------------- stage wrappers ----------------------------------------------
__global__ __launch_bounds__(256) void k_pw(const float* __restrict__ P,
                                            const float* __restrict__ Waff) {
    int bh = blockIdx.z;
    gemm_core<0, 1, 0>(P + (size_t)(bh >> 3) * L1c * Dc,
                       Waff + (size_t)(bh & 7) * Dc * Dc,
                       g_T + (size_t)bh * L1c * Dc,
                       Dc, Dc, Dc, Dc, nullptr, nullptr, nullptr, nullptr);
}
__global__ __launch_bounds__(256) void k_aff(const float* __restrict__ S,
                                             const float* __restrict__ pm,
                                             const float* __restrict__ sm_) {
    int bh = blockIdx.z, b = bh >> 3;
    gemm_core<0, 0, 1>(g_T + (size_t)bh * L1c * Dc,
                       S + (size_t)b * L2c * Dc,
                       g_aff + (size_t)bh * L1c * L2c,
                       Dc, Dc, Dc, L2c, nullptr,
                       pm + b * L1c, sm_ + b * L2c, nullptr);
}
__global__ __launch_bounds__(256) void k_projP(const float* __restrict__ X,
                                               const float* __restrict__ W) {
    int b = blockIdx.z;
    gemm_core<0, 1, 0>(X + (size_t)b * L1c * Dc, W,
                       g_PP + (size_t)b * L1c * INNERc,
                       Dc, Dc, INNERc, INNERc, nullptr, nullptr, nullptr, nullptr);
}
__global__ __launch_bounds__(256) void k_projS(const float* __restrict__ X,
                                               const float* __restrict__ W) {
    int b = blockIdx.z;
    gemm_core<0, 1, 0>(X + (size_t)b * L2c * Dc, W,
                       g_PS + (size_t)b * L2c * INNERc,
                       Dc, Dc, INNERc, INNERc, nullptr, nullptr, nullptr, nullptr);
}
// wp[j,d] = relu(sum_i aff[i,j] pp[i,d]) : A=aff [K=i][M=j] TR, B=pp [K=i][N=d] TR
__global__ __launch_bounds__(256) void k_wp() {
    int bh = blockIdx.z, b = bh >> 3, h = bh & 7;
    gemm_core<1, 1, 2>(g_aff + (size_t)bh * L1c * L2c,
                       g_PP + (size_t)b * L1c * INNERc + h * HDc,
                       g_wp + (size_t)bh * L2c * HDc,
                       L1c, L2c, INNERc, HDc, nullptr, nullptr, nullptr, nullptr);
}
// ws[i,d] = relu(sum_j aff[i,j] ps[j,d]) : A=aff [M=i][K=j], B=ps [K=j][N=d] TR
__global__ __launch_bounds__(256) void k_ws() {
    int bh = blockIdx.z, b = bh >> 3, h = bh & 7;
    gemm_core<0, 1, 2>(g_aff + (size_t)bh * L1c * L2c,
                       g_PS + (size_t)b * L2c * INNERc + h * HDc,
                       g_ws + (size_t)bh * L1c * HDc,
                       L2c, L2c, INNERc, HDc, nullptr, nullptr, nullptr, nullptr);
}
// FFN with fused concat: A = [X | pool] (AMODE 2), B = W [K][N] TR
__global__ __launch_bounds__(256) void k_ffnp(const float* __restrict__ P,
                                              const float* __restrict__ W,
                                              const float* __restrict__ bias,
                                              float* __restrict__ O) {
    int b = blockIdx.z;
    gemm_core<2, 1, 3>(P + (size_t)b * L1c * Dc, W,
                       O + (size_t)b * L1c * Dc,
                       DCc, Dc, Dc, Dc,
                       g_pools + (size_t)b * L1c * HDc, nullptr, nullptr, bias);
}
__global__ __launch_bounds__(256) void k_ffns(const float* __restrict__ S,
                                              const float* __restrict__ W,
                                              const float* __restrict__ bias,
                                              float* __restrict__ O) {
    int b = blockIdx.z;
    gemm_core<2, 1, 3>(S + (size_t)b * L2c * Dc, W,
                       O + (size_t)b * L2c * Dc,
                       DCc, Dc, Dc, Dc,
                       g_poolp + (size_t)b * L2c * HDc, nullptr, nullptr, bias);
}

// ---------------- elementwise stages ------------------------------------------
__global__ void k_poolp() {
    int idx = blockIdx.x * blockDim.x + threadIdx.x;
    const int tot = Bc * L2c * HDc;
    if (idx >= tot) return;
    int b = idx / (L2c * HDc);
    int r = idx - b * (L2c * HDc);
    float m = g_wp[((size_t)b * Hc) * L2c * HDc + r];
    #pragma unroll
    for (int h = 1; h < Hc; h++)
        m = fmaxf(m, g_wp[((size_t)(b * Hc + h)) * L2c * HDc + r]);
    g_poolp[idx] = m;
}
__global__ void k_pools() {
    int idx = blockIdx.x * blockDim.x + threadIdx.x;
    const int tot = Bc * L1c * HDc;
    if (idx >= tot) return;
    int b = idx / (L1c * HDc);
    int r = idx - b * (L1c * HDc);
    float m = g_ws[((size_t)b * Hc) * L1c * HDc + r];
    #pragma unroll
    for (int h = 1; h < Hc; h++)
        m = fmaxf(m, g_ws[((size_t)(b * Hc + h)) * L1c * HDc + r]);
    g_pools[idx] = m;
}

// ---------------- launcher ----------------------------------------------------
extern "C" void kernel_launch(void* const* d_in, const int* in_sizes, int n_in,
                              void* d_out, int out_size) {
    const float* P    = (const float*)d_in[0];
    const float* S    = (const float*)d_in[1];
    const float* pm   = (const float*)d_in[2];
    const float* sm   = (const float*)d_in[3];
    const float* Waff = (const float*)d_in[4];
    const float* Wp   = (const float*)d_in[5];
    const float* Ws   = (const float*)d_in[6];
    const float* Wfp  = (const float*)d_in[7];
    const float* bfp  = (const float*)d_in[8];
    const float* Wfs  = (const float*)d_in[9];
    const float* bfs  = (const float*)d_in[10];

    float* outp = (float*)d_out;
    float* outs = outp + (size_t)Bc * L1c * Dc;

    static int inited = 0;
    if (!inited) {
        cudaFuncSetAttribute(k_pw,    cudaFuncAttributeMaxDynamicSharedMemorySize, SMEM_TOT);
        cudaFuncSetAttribute(k_aff,   cudaFuncAttributeMaxDynamicSharedMemorySize, SMEM_TOT);
        cudaFuncSetAttribute(k_projP, cudaFuncAttributeMaxDynamicSharedMemorySize, SMEM_TOT);
        cudaFuncSetAttribute(k_projS, cudaFuncAttributeMaxDynamicSharedMemorySize, SMEM_TOT);
        cudaFuncSetAttribute(k_wp,    cudaFuncAttributeMaxDynamicSharedMemorySize, SMEM_TOT);
        cudaFuncSetAttribute(k_ws,    cudaFuncAttributeMaxDynamicSharedMemorySize, SMEM_TOT);
        cudaFuncSetAttribute(k_ffnp,  cudaFuncAttributeMaxDynamicSharedMemorySize, SMEM_TOT);
        cudaFuncSetAttribute(k_ffns,  cudaFuncAttributeMaxDynamicSharedMemorySize, SMEM_TOT);
        inited = 1;
    }

    dim3 blk(256);

    k_pw   <<<dim3(4, 4, Bc * Hc), blk, SMEM_TOT>>>(P, Waff);
    k_aff  <<<dim3(4, 4, Bc * Hc), blk, SMEM_TOT>>>(S, pm, sm);
    k_projP<<<dim3(8, 4, Bc),      blk, SMEM_TOT>>>(P, Wp);
    k_projS<<<dim3(8, 4, Bc),      blk, SMEM_TOT>>>(S, Ws);
    k_wp   <<<dim3(1, 4, Bc * Hc), blk, SMEM_TOT>>>();
    k_ws   <<<dim3(1, 4, Bc * Hc), blk, SMEM_TOT>>>();

    { int tot = Bc * L2c * HDc; k_poolp<<<(tot + 255) / 256, 256>>>(); }
    { int tot = Bc * L1c * HDc; k_pools<<<(tot + 255) / 256, 256>>>(); }

    k_ffnp <<<dim3(4, 4, Bc), blk, SMEM_TOT>>>(P, Wfp, bfp, outp);
    k_ffns <<<dim3(4, 4, Bc), blk, SMEM_TOT>>>(S, Wfs, bfs, outs);
}

// round 6
// speedup vs baseline: 3.9079x; 1.6803x over previous
#include <cuda_runtime.h>
#include <cuda_fp16.h>
#include <mma.h>
#include <math.h>
#include <stdint.h>

using namespace nvcuda;

// Problem constants
#define Bc     16
#define L1c    512
#define L2c    512
#define Dc     512
#define Hc     8
#define INNERc 1024
#define HDc    128
#define DCc    640   // D + HD

// ---------------- fp16 hi/lo pair scratch (static device globals) -------------
// NOTE: __align__(256) — cp.async 16B + vector loads require >=16B alignment;
// bare __half arrays only guarantee 2B.
__device__ __align__(256) __half g_Ph [(size_t)Bc*L1c*Dc];
__device__ __align__(256) __half g_Pl [(size_t)Bc*L1c*Dc];
__device__ __align__(256) __half g_Sh [(size_t)Bc*L2c*Dc];
__device__ __align__(256) __half g_Sl [(size_t)Bc*L2c*Dc];
__device__ __align__(256) __half g_WaffTh[(size_t)Hc*Dc*Dc];
__device__ __align__(256) __half g_WaffTl[(size_t)Hc*Dc*Dc];
__device__ __align__(256) __half g_WpTh[(size_t)INNERc*Dc];
__device__ __align__(256) __half g_WpTl[(size_t)INNERc*Dc];
__device__ __align__(256) __half g_WsTh[(size_t)INNERc*Dc];
__device__ __align__(256) __half g_WsTl[(size_t)INNERc*Dc];
__device__ __align__(256) __half g_WfpTh[(size_t)Dc*DCc];
__device__ __align__(256) __half g_WfpTl[(size_t)Dc*DCc];
__device__ __align__(256) __half g_WfsTh[(size_t)Dc*DCc];
__device__ __align__(256) __half g_WfsTl[(size_t)Dc*DCc];
__device__ __align__(256) __half g_Th  [(size_t)Bc*Hc*L1c*Dc];
__device__ __align__(256) __half g_Tl  [(size_t)Bc*Hc*L1c*Dc];
__device__ __align__(256) __half g_affh [(size_t)Bc*Hc*L1c*L2c];
__device__ __align__(256) __half g_affl [(size_t)Bc*Hc*L1c*L2c];
__device__ __align__(256) __half g_affTh[(size_t)Bc*Hc*L2c*L1c];
__device__ __align__(256) __half g_affTl[(size_t)Bc*Hc*L2c*L1c];
__device__ __align__(256) __half g_PPTh[(size_t)Bc*INNERc*L1c];
__device__ __align__(256) __half g_PPTl[(size_t)Bc*INNERc*L1c];
__device__ __align__(256) __half g_PSTh[(size_t)Bc*INNERc*L2c];
__device__ __align__(256) __half g_PSTl[(size_t)Bc*INNERc*L2c];
__device__ __align__(256) float  g_wp [(size_t)Bc*Hc*L2c*HDc];
__device__ __align__(256) float  g_ws [(size_t)Bc*Hc*L1c*HDc];
__device__ __align__(256) __half g_poolph[(size_t)Bc*L2c*HDc];
__device__ __align__(256) __half g_poolpl[(size_t)Bc*L2c*HDc];
__device__ __align__(256) __half g_poolsh[(size_t)Bc*L1c*HDc];
__device__ __align__(256) __half g_poolsl[(size_t)Bc*L1c*HDc];

// ---------------- helpers -----------------------------------------------------
__device__ __forceinline__ uint32_t smem_u32(const void* p) {
    uint32_t a;
    asm("{ .reg .u64 t; cvta.to.shared.u64 t, %1; cvt.u32.u64 %0, t; }" : "=r"(a) : "l"(p));
    return a;
}
__device__ __forceinline__ void cpa16(uint32_t dst, const void* src) {
    asm volatile("cp.async.cg.shared.global [%0], [%1], 16;" :: "r"(dst), "l"(src));
}
__device__ __forceinline__ void cpa_commit() { asm volatile("cp.async.commit_group;" ::: "memory"); }
__device__ __forceinline__ void cpa_wait1()  { asm volatile("cp.async.wait_group 1;" ::: "memory"); }
__device__ __forceinline__ void cpa_wait0()  { asm volatile("cp.async.wait_group 0;" ::: "memory"); }

__device__ __forceinline__ void split2(float x, __half& h, __half& l) {
    h = __float2half_rn(x);
    l = __float2half_rn(x - __half2float(h));
}

// fp16 tile: 128 rows x 32 halves, row stride 40 halves (80 B).
#define TLD16   40
#define TILEB   10240              // bytes per tile
#define BUFB    40960              // Ah,Al,Bh,Bl per buffer
#define SMEM_TOT 81920             // double-buffered
#define CSLD    132                // f32 epilogue smem stride

// ---- staging: global fp16 rows -> smem tile via cp.async ---------------------
// MODE 0: G[(rb+m)*ld + k]    MODE 1: concat, k<Dc from G(ld=Dc) else pool(ld=HDc)
template<int MODE>
__device__ __forceinline__ void stage16(const __half* __restrict__ G, int ld,
                                        const __half* __restrict__ pool,
                                        int rb, int k0, uint32_t dst) {
    const int tid = threadIdx.x;
    #pragma unroll
    for (int r = 0; r < 2; r++) {
        int idx = r * 256 + tid;
        int m   = idx >> 2;
        int kq  = (idx & 3) << 3;
        const __half* src;
        if (MODE == 0) {
            src = G + (size_t)(rb + m) * ld + k0 + kq;
        } else {
            int gk = k0 + kq;
            src = (gk < Dc) ? G    + (size_t)(rb + m) * Dc  + gk
                            : pool + (size_t)(rb + m) * HDc + (gk - Dc);
        }
        cpa16(dst + m * 80 + kq * 2, src);
    }
}

typedef wmma::fragment<wmma::matrix_a, 16, 16, 16, __half, wmma::row_major> FragA;
typedef wmma::fragment<wmma::matrix_b, 16, 16, 16, __half, wmma::col_major> FragB;
typedef wmma::fragment<wmma::accumulator, 16, 16, 16, float> FragC;

// ---------------- core GEMM ---------------------------------------------------
// C(128x128 tile) = A(MxK) x B(KxN). A,B given as fp16 hi/lo row-tiles.
// PASSES 3: AhBh+AlBh+AhBl. PASSES 2: AhBh+AlBh.
// EPI 0: split-write hi/lo.  EPI 1: tanh*rs*cs -> aff h/l + affT h/l.
// EPI 2: relu -> f32.        EPI 3: relu(+bias) -> f32.
template<int PASSES, int AMODE, int EPI>
__device__ __forceinline__ void gemm_core(
    const __half* __restrict__ Ah_g, const __half* __restrict__ Al_g,
    const __half* __restrict__ aph,  const __half* __restrict__ apl,
    const __half* __restrict__ Bh_g, const __half* __restrict__ Bl_g,
    float* __restrict__ Cf, __half* __restrict__ Ch, __half* __restrict__ Cl,
    __half* __restrict__ CTh, __half* __restrict__ CTl, int ldct,
    int K, int lda, int ldb, int ldc,
    const float* __restrict__ rs, const float* __restrict__ cs,
    const float* __restrict__ bias)
{
    extern __shared__ char smc[];
    const uint32_t smb = smem_u32(smc);

    const int tid  = threadIdx.x;
    const int wid  = tid >> 5;
    const int lane = tid & 31;
    const int wm   = wid & 3;
    const int wn   = wid >> 2;
    const int row0 = blockIdx.y * 128;
    const int col0 = blockIdx.x * 128;

    FragC acc[2][4];
    #pragma unroll
    for (int i = 0; i < 2; i++)
        #pragma unroll
        for (int j = 0; j < 4; j++) wmma::fill_fragment(acc[i][j], 0.0f);

    const int NCH = K >> 5;

    {
        uint32_t b0 = smb;
        stage16<AMODE>(Ah_g, lda, aph, row0, 0, b0);
        stage16<AMODE>(Al_g, lda, apl, row0, 0, b0 + TILEB);
        stage16<0>(Bh_g, ldb, nullptr, col0, 0, b0 + 2 * TILEB);
        stage16<0>(Bl_g, ldb, nullptr, col0, 0, b0 + 3 * TILEB);
        cpa_commit();
    }

    for (int c = 0; c < NCH; c++) {
        if (c + 1 < NCH) {
            uint32_t nb = smb + ((c + 1) & 1) * BUFB;
            int k0 = (c + 1) << 5;
            stage16<AMODE>(Ah_g, lda, aph, row0, k0, nb);
            stage16<AMODE>(Al_g, lda, apl, row0, k0, nb + TILEB);
            stage16<0>(Bh_g, ldb, nullptr, col0, k0, nb + 2 * TILEB);
            stage16<0>(Bl_g, ldb, nullptr, col0, k0, nb + 3 * TILEB);
            cpa_commit();
            cpa_wait1();
        } else {
            cpa_wait0();
        }
        __syncthreads();

        const __half* Ahs = (const __half*)(smc + (c & 1) * BUFB);
        const __half* Als = Ahs + 5120;
        const __half* Bhs = Ahs + 10240;
        const __half* Bls = Ahs + 15360;

        #pragma unroll
        for (int ks = 0; ks < 2; ks++) {
            FragA fah[2], fal[2];
            #pragma unroll
            for (int ti = 0; ti < 2; ti++) {
                int ro = (wm * 32 + ti * 16) * TLD16 + ks * 16;
                wmma::load_matrix_sync(fah[ti], Ahs + ro, TLD16);
                wmma::load_matrix_sync(fal[ti], Als + ro, TLD16);
            }
            #pragma unroll
            for (int tj = 0; tj < 4; tj++) {
                int co = (wn * 64 + tj * 16) * TLD16 + ks * 16;
                FragB fbh;
                wmma::load_matrix_sync(fbh, Bhs + co, TLD16);
                #pragma unroll
                for (int ti = 0; ti < 2; ti++) {
                    wmma::mma_sync(acc[ti][tj], fah[ti], fbh, acc[ti][tj]);
                    wmma::mma_sync(acc[ti][tj], fal[ti], fbh, acc[ti][tj]);
                }
                if (PASSES == 3) {
                    FragB fbl;
                    wmma::load_matrix_sync(fbl, Bls + co, TLD16);
                    #pragma unroll
                    for (int ti = 0; ti < 2; ti++)
                        wmma::mma_sync(acc[ti][tj], fah[ti], fbl, acc[ti][tj]);
                }
            }
        }
        __syncthreads();
    }

    // ---------------- epilogue through smem -----------------------------------
    float* Cs = (float*)smc;
    #pragma unroll
    for (int ti = 0; ti < 2; ti++)
        #pragma unroll
        for (int tj = 0; tj < 4; tj++)
            wmma::store_matrix_sync(Cs + (wm * 32 + ti * 16) * CSLD + wn * 64 + tj * 16,
                                    acc[ti][tj], CSLD, wmma::mem_row_major);
    __syncthreads();

    #pragma unroll
    for (int it = 0; it < 16; it++) {
        int row = it * 8 + wid;
        float4 v = *(float4*)(Cs + row * CSLD + lane * 4);
        if (EPI == 0) {
            __half h0, h1, h2, h3, l0, l1, l2, l3;
            split2(v.x, h0, l0); split2(v.y, h1, l1);
            split2(v.z, h2, l2); split2(v.w, h3, l3);
            size_t off = (size_t)(row0 + row) * ldc + col0 + lane * 4;
            *(__half2*)(Ch + off)     = __halves2half2(h0, h1);
            *(__half2*)(Ch + off + 2) = __halves2half2(h2, h3);
            *(__half2*)(Cl + off)     = __halves2half2(l0, l1);
            *(__half2*)(Cl + off + 2) = __halves2half2(l2, l3);
        } else if (EPI == 1) {
            float rm = rs[row0 + row];
            v.x = tanhf(v.x) * rm * cs[col0 + lane * 4 + 0];
            v.y = tanhf(v.y) * rm * cs[col0 + lane * 4 + 1];
            v.z = tanhf(v.z) * rm * cs[col0 + lane * 4 + 2];
            v.w = tanhf(v.w) * rm * cs[col0 + lane * 4 + 3];
            *(float4*)(Cs + row * CSLD + lane * 4) = v;   // for transposed pass
            __half h0, h1, h2, h3, l0, l1, l2, l3;
            split2(v.x, h0, l0); split2(v.y, h1, l1);
            split2(v.z, h2, l2); split2(v.w, h3, l3);
            size_t off = (size_t)(row0 + row) * ldc + col0 + lane * 4;
            *(__half2*)(Ch + off)     = __halves2half2(h0, h1);
            *(__half2*)(Ch + off + 2) = __halves2half2(h2, h3);
            *(__half2*)(Cl + off)     = __halves2half2(l0, l1);
            *(__half2*)(Cl + off + 2) = __halves2half2(l2, l3);
        } else if (EPI == 2) {
            v.x = fmaxf(v.x, 0.f); v.y = fmaxf(v.y, 0.f);
            v.z = fmaxf(v.z, 0.f); v.w = fmaxf(v.w, 0.f);
            *(float4*)(Cf + (size_t)(row0 + row) * ldc + col0 + lane * 4) = v;
        } else {
            v.x = fmaxf(v.x + bias[col0 + lane * 4 + 0], 0.f);
            v.y = fmaxf(v.y + bias[col0 + lane * 4 + 1], 0.f);
            v.z = fmaxf(v.z + bias[col0 + lane * 4 + 2], 0.f);
            v.w = fmaxf(v.w + bias[col0 + lane * 4 + 3], 0.f);
            *(float4*)(Cf + (size_t)(row0 + row) * ldc + col0 + lane * 4) = v;
        }
    }

    if (EPI == 1) {
        __syncthreads();
        #pragma unroll
        for (int ct = 0; ct < 16; ct++) {
            int col = ct * 8 + wid;
            #pragma unroll
            for (int cc = 0; cc < 4; cc++) {
                int r = cc * 32 + lane;
                float x = Cs[r * CSLD + col];
                __half h, l;
                split2(x, h, l);
                size_t off = (size_t)(col0 + col) * ldct + row0 + r;
                CTh[off] = h;
                CTl[off] = l;
            }
        }
    }
}

// ---------------- GEMM kernels ------------------------------------------------
__global__ __launch_bounds__(256, 2) void k_pw() {
    int bh = blockIdx.z;
    gemm_core<3, 0, 0>(g_Ph + (size_t)(bh >> 3) * L1c * Dc,
                       g_Pl + (size_t)(bh >> 3) * L1c * Dc, nullptr, nullptr,
                       g_WaffTh + (size_t)(bh & 7) * Dc * Dc,
                       g_WaffTl + (size_t)(bh & 7) * Dc * Dc,
                       nullptr, g_Th + (size_t)bh * L1c * Dc,
                       g_Tl + (size_t)bh * L1c * Dc,
                       nullptr, nullptr, 0,
                       Dc, Dc, Dc, Dc, nullptr, nullptr, nullptr);
}
__global__ __launch_bounds__(256, 2) void k_aff(const float* __restrict__ pm,
                                                const float* __restrict__ sm_) {
    int bh = blockIdx.z, b = bh >> 3;
    gemm_core<3, 0, 1>(g_Th + (size_t)bh * L1c * Dc,
                       g_Tl + (size_t)bh * L1c * Dc, nullptr, nullptr,
                       g_Sh + (size_t)b * L2c * Dc,
                       g_Sl + (size_t)b * L2c * Dc,
                       nullptr,
                       g_affh + (size_t)bh * L1c * L2c,
                       g_affl + (size_t)bh * L1c * L2c,
                       g_affTh + (size_t)bh * L2c * L1c,
                       g_affTl + (size_t)bh * L2c * L1c, L1c,
                       Dc, Dc, Dc, L2c,
                       pm + b * L1c, sm_ + b * L2c, nullptr);
}
__global__ __launch_bounds__(256, 2) void k_projP() {
    int b = blockIdx.z;
    gemm_core<2, 0, 0>(g_WpTh, g_WpTl, nullptr, nullptr,
                       g_Ph + (size_t)b * L1c * Dc, g_Pl + (size_t)b * L1c * Dc,
                       nullptr,
                       g_PPTh + (size_t)b * INNERc * L1c,
                       g_PPTl + (size_t)b * INNERc * L1c,
                       nullptr, nullptr, 0,
                       Dc, Dc, Dc, L1c, nullptr, nullptr, nullptr);
}
__global__ __launch_bounds__(256, 2) void k_projS() {
    int b = blockIdx.z;
    gemm_core<2, 0, 0>(g_WsTh, g_WsTl, nullptr, nullptr,
                       g_Sh + (size_t)b * L2c * Dc, g_Sl + (size_t)b * L2c * Dc,
                       nullptr,
                       g_PSTh + (size_t)b * INNERc * L2c,
                       g_PSTl + (size_t)b * INNERc * L2c,
                       nullptr, nullptr, 0,
                       Dc, Dc, Dc, L2c, nullptr, nullptr, nullptr);
}
__global__ __launch_bounds__(256, 2) void k_wp() {
    int bh = blockIdx.z, b = bh >> 3, h = bh & 7;
    gemm_core<2, 0, 2>(g_affTh + (size_t)bh * L2c * L1c,
                       g_affTl + (size_t)bh * L2c * L1c, nullptr, nullptr,
                       g_PPTh + (size_t)b * INNERc * L1c + (size_t)h * HDc * L1c,
                       g_PPTl + (size_t)b * INNERc * L1c + (size_t)h * HDc * L1c,
                       g_wp + (size_t)bh * L2c * HDc, nullptr, nullptr,
                       nullptr, nullptr, 0,
                       L1c, L1c, L1c, HDc, nullptr, nullptr, nullptr);
}
__global__ __launch_bounds__(256, 2) void k_ws() {
    int bh = blockIdx.z, b = bh >> 3, h = bh & 7;
    gemm_core<2, 0, 2>(g_affh + (size_t)bh * L1c * L2c,
                       g_affl + (size_t)bh * L1c * L2c, nullptr, nullptr,
                       g_PSTh + (size_t)b * INNERc * L2c + (size_t)h * HDc * L2c,
                       g_PSTl + (size_t)b * INNERc * L2c + (size_t)h * HDc * L2c,
                       g_ws + (size_t)bh * L1c * HDc, nullptr, nullptr,
                       nullptr, nullptr, 0,
                       L2c, L2c, L2c, HDc, nullptr, nullptr, nullptr);
}
__global__ __launch_bounds__(256, 2) void k_ffnp(const float* __restrict__ bias,
                                                 float* __restrict__ O) {
    int b = blockIdx.z;
    gemm_core<2, 1, 3>(g_Ph + (size_t)b * L1c * Dc, g_Pl + (size_t)b * L1c * Dc,
                       g_poolsh + (size_t)b * L1c * HDc,
                       g_poolsl + (size_t)b * L1c * HDc,
                       g_WfpTh, g_WfpTl,
                       O + (size_t)b * L1c * Dc, nullptr, nullptr,
                       nullptr, nullptr, 0,
                       DCc, Dc, DCc, Dc, nullptr, nullptr, bias);
}
__global__ __launch_bounds__(256, 2) void k_ffns(const float* __restrict__ bias,
                                                 float* __restrict__ O) {
    int b = blockIdx.z;
    gemm_core<2, 1, 3>(g_Sh + (size_t)b * L2c * Dc, g_Sl + (size_t)b * L2c * Dc,
                       g_poolph + (size_t)b * L2c * HDc,
                       g_poolpl + (size_t)b * L2c * HDc,
                       g_WfsTh, g_WfsTl,
                       O + (size_t)b * L2c * Dc, nullptr, nullptr,
                       nullptr, nullptr, 0,
                       DCc, Dc, DCc, Dc, nullptr, nullptr, bias);
}

// ---------------- conversion kernels ------------------------------------------
__global__ void k_split(const float* __restrict__ X,
                        __half* __restrict__ H, __half* __restrict__ L, int n) {
    int i = (blockIdx.x * blockDim.x + threadIdx.x) * 4;
    if (i >= n) return;
    float4 v = *(const float4*)(X + i);
    __half h0, h1, h2, h3, l0, l1, l2, l3;
    split2(v.x, h0, l0); split2(v.y, h1, l1);
    split2(v.z, h2, l2); split2(v.w, h3, l3);
    *(__half2*)(H + i)     = __halves2half2(h0, h1);
    *(__half2*)(H + i + 2) = __halves2half2(h2, h3);
    *(__half2*)(L + i)     = __halves2half2(l0, l1);
    *(__half2*)(L + i + 2) = __halves2half2(l2, l3);
}

// transpose + split: X[z][R][C] f32 -> H/L [z][C][R] fp16
__global__ void k_splitT(const float* __restrict__ X,
                         __half* __restrict__ H, __half* __restrict__ L,
                         int R, int C) {
    __shared__ float t[32][33];
    int z = blockIdx.z;
    int x0 = blockIdx.x * 32;
    int y0 = blockIdx.y * 32;
    const float* Xz = X + (size_t)z * R * C;
    #pragma unroll
    for (int i = 0; i < 4; i++) {
        int r = y0 + threadIdx.y * 4 + i;
        t[threadIdx.y * 4 + i][threadIdx.x] = Xz[(size_t)r * C + x0 + threadIdx.x];
    }
    __syncthreads();
    size_t zb = (size_t)z * R * C;
    #pragma unroll
    for (int i = 0; i < 4; i++) {
        int oc = x0 + threadIdx.y * 4 + i;
        float v = t[threadIdx.x][threadIdx.y * 4 + i];
        __half h, l;
        split2(v, h, l);
        H[zb + (size_t)oc * R + y0 + threadIdx.x] = h;
        L[zb + (size_t)oc * R + y0 + threadIdx.x] = l;
    }
}

// ---------------- pools --------------------------------------------------------
__global__ void k_poolp() {
    int idx = blockIdx.x * blockDim.x + threadIdx.x;
    const int tot = Bc * L2c * HDc;
    if (idx >= tot) return;
    int b = idx / (L2c * HDc);
    int r = idx - b * (L2c * HDc);
    float m = g_wp[((size_t)b * Hc) * L2c * HDc + r];
    #pragma unroll
    for (int h = 1; h < Hc; h++)
        m = fmaxf(m, g_wp[((size_t)(b * Hc + h)) * L2c * HDc + r]);
    __half hh, ll;
    split2(m, hh, ll);
    g_poolph[idx] = hh;
    g_poolpl[idx] = ll;
}
__global__ void k_pools() {
    int idx = blockIdx.x * blockDim.x + threadIdx.x;
    const int tot = Bc * L1c * HDc;
    if (idx >= tot) return;
    int b = idx / (L1c * HDc);
    int r = idx - b * (L1c * HDc);
    float m = g_ws[((size_t)b * Hc) * L1c * HDc + r];
    #pragma unroll
    for (int h = 1; h < Hc; h++)
        m = fmaxf(m, g_ws[((size_t)(b * Hc + h)) * L1c * HDc + r]);
    __half hh, ll;
    split2(m, hh, ll);
    g_poolsh[idx] = hh;
    g_poolsl[idx] = ll;
}

// ---------------- launcher -----------------------------------------------------
template<typename T>
static T* sym_addr(const void* sym) {
    void* p = nullptr;
    cudaGetSymbolAddress(&p, sym);     // host-side query: capture-safe, no alloc
    return (T*)p;
}

extern "C" void kernel_launch(void* const* d_in, const int* in_sizes, int n_in,
                              void* d_out, int out_size) {
    const float* P    = (const float*)d_in[0];
    const float* S    = (const float*)d_in[1];
    const float* pm   = (const float*)d_in[2];
    const float* sm   = (const float*)d_in[3];
    const float* Waff = (const float*)d_in[4];
    const float* Wp   = (const float*)d_in[5];
    const float* Ws   = (const float*)d_in[6];
    const float* Wfp  = (const float*)d_in[7];
    const float* bfp  = (const float*)d_in[8];
    const float* Wfs  = (const float*)d_in[9];
    const float* bfs  = (const float*)d_in[10];

    float* outp = (float*)d_out;
    float* outs = outp + (size_t)Bc * L1c * Dc;

    // real device addresses of __device__ globals (host shadow symbols are NOT
    // valid device pointers — round-5 bug)
    __half* Ph     = sym_addr<__half>(g_Ph);
    __half* Pl     = sym_addr<__half>(g_Pl);
    __half* Sh     = sym_addr<__half>(g_Sh);
    __half* Sl     = sym_addr<__half>(g_Sl);
    __half* WaffTh = sym_addr<__half>(g_WaffTh);
    __half* WaffTl = sym_addr<__half>(g_WaffTl);
    __half* WpTh   = sym_addr<__half>(g_WpTh);
    __half* WpTl   = sym_addr<__half>(g_WpTl);
    __half* WsTh   = sym_addr<__half>(g_WsTh);
    __half* WsTl   = sym_addr<__half>(g_WsTl);
    __half* WfpTh  = sym_addr<__half>(g_WfpTh);
    __half* WfpTl  = sym_addr<__half>(g_WfpTl);
    __half* WfsTh  = sym_addr<__half>(g_WfsTh);
    __half* WfsTl  = sym_addr<__half>(g_WfsTl);

    cudaFuncSetAttribute(k_pw,    cudaFuncAttributeMaxDynamicSharedMemorySize, SMEM_TOT);
    cudaFuncSetAttribute(k_aff,   cudaFuncAttributeMaxDynamicSharedMemorySize, SMEM_TOT);
    cudaFuncSetAttribute(k_projP, cudaFuncAttributeMaxDynamicSharedMemorySize, SMEM_TOT);
    cudaFuncSetAttribute(k_projS, cudaFuncAttributeMaxDynamicSharedMemorySize, SMEM_TOT);
    cudaFuncSetAttribute(k_wp,    cudaFuncAttributeMaxDynamicSharedMemorySize, SMEM_TOT);
    cudaFuncSetAttribute(k_ws,    cudaFuncAttributeMaxDynamicSharedMemorySize, SMEM_TOT);
    cudaFuncSetAttribute(k_ffnp,  cudaFuncAttributeMaxDynamicSharedMemorySize, SMEM_TOT);
    cudaFuncSetAttribute(k_ffns,  cudaFuncAttributeMaxDynamicSharedMemorySize, SMEM_TOT);

    // input conversions
    {
        int n = Bc * L1c * Dc;
        k_split<<<n / 1024, 256>>>(P, Ph, Pl, n);
        k_split<<<n / 1024, 256>>>(S, Sh, Sl, n);
    }
    k_splitT<<<dim3(Dc / 32, Dc / 32, Hc), dim3(32, 8)>>>(Waff, WaffTh, WaffTl, Dc, Dc);
    k_splitT<<<dim3(INNERc / 32, Dc / 32, 1), dim3(32, 8)>>>(Wp, WpTh, WpTl, Dc, INNERc);
    k_splitT<<<dim3(INNERc / 32, Dc / 32, 1), dim3(32, 8)>>>(Ws, WsTh, WsTl, Dc, INNERc);
    k_splitT<<<dim3(Dc / 32, DCc / 32, 1), dim3(32, 8)>>>(Wfp, WfpTh, WfpTl, DCc, Dc);
    k_splitT<<<dim3(Dc / 32, DCc / 32, 1), dim3(32, 8)>>>(Wfs, WfsTh, WfsTl, DCc, Dc);

    dim3 blk(256);

    k_pw   <<<dim3(4, 4, Bc * Hc), blk, SMEM_TOT>>>();
    k_aff  <<<dim3(4, 4, Bc * Hc), blk, SMEM_TOT>>>(pm, sm);
    k_projP<<<dim3(4, 8, Bc),      blk, SMEM_TOT>>>();
    k_projS<<<dim3(4, 8, Bc),      blk, SMEM_TOT>>>();
    k_wp   <<<dim3(1, 4, Bc * Hc), blk, SMEM_TOT>>>();
    k_ws   <<<dim3(1, 4, Bc * Hc), blk, SMEM_TOT>>>();

    { int tot = Bc * L2c * HDc; k_poolp<<<(tot + 255) / 256, 256>>>(); }
    { int tot = Bc * L1c * HDc; k_pools<<<(tot + 255) / 256, 256>>>(); }

    k_ffnp <<<dim3(4, 4, Bc), blk, SMEM_TOT>>>(bfp, outp);
    k_ffns <<<dim3(4, 4, Bc), blk, SMEM_TOT>>>(bfs, outs);
}

// round 7
// speedup vs baseline: 4.2011x; 1.0750x over previous
#include <cuda_runtime.h>
#include <cuda_fp16.h>
#include <mma.h>
#include <math.h>
#include <stdint.h>

using namespace nvcuda;

// Problem constants
#define Bc     16
#define L1c    512
#define L2c    512
#define Dc     512
#define Hc     8
#define INNERc 1024
#define HDc    128
#define DCc    640   // D + HD

// ---------------- fp16 hi/lo pair scratch (static device globals) -------------
__device__ __align__(256) __half g_Ph [(size_t)Bc*L1c*Dc];
__device__ __align__(256) __half g_Pl [(size_t)Bc*L1c*Dc];
__device__ __align__(256) __half g_Sh [(size_t)Bc*L2c*Dc];
__device__ __align__(256) __half g_Sl [(size_t)Bc*L2c*Dc];
__device__ __align__(256) __half g_WaffTh[(size_t)Hc*Dc*Dc];
__device__ __align__(256) __half g_WaffTl[(size_t)Hc*Dc*Dc];
__device__ __align__(256) __half g_WpTh[(size_t)INNERc*Dc];
__device__ __align__(256) __half g_WpTl[(size_t)INNERc*Dc];
__device__ __align__(256) __half g_WsTh[(size_t)INNERc*Dc];
__device__ __align__(256) __half g_WsTl[(size_t)INNERc*Dc];
__device__ __align__(256) __half g_WfpTh[(size_t)Dc*DCc];
__device__ __align__(256) __half g_WfpTl[(size_t)Dc*DCc];
__device__ __align__(256) __half g_WfsTh[(size_t)Dc*DCc];
__device__ __align__(256) __half g_WfsTl[(size_t)Dc*DCc];
__device__ __align__(256) __half g_Th  [(size_t)Bc*Hc*L1c*Dc];
__device__ __align__(256) __half g_Tl  [(size_t)Bc*Hc*L1c*Dc];
__device__ __align__(256) __half g_affh [(size_t)Bc*Hc*L1c*L2c];
__device__ __align__(256) __half g_affl [(size_t)Bc*Hc*L1c*L2c];
__device__ __align__(256) __half g_affTh[(size_t)Bc*Hc*L2c*L1c];
__device__ __align__(256) __half g_affTl[(size_t)Bc*Hc*L2c*L1c];
__device__ __align__(256) __half g_PPTh[(size_t)Bc*INNERc*L1c];
__device__ __align__(256) __half g_PPTl[(size_t)Bc*INNERc*L1c];
__device__ __align__(256) __half g_PSTh[(size_t)Bc*INNERc*L2c];
__device__ __align__(256) __half g_PSTl[(size_t)Bc*INNERc*L2c];
__device__ __align__(256) float  g_wp [(size_t)Bc*Hc*L2c*HDc];
__device__ __align__(256) float  g_ws [(size_t)Bc*Hc*L1c*HDc];
__device__ __align__(256) __half g_poolph[(size_t)Bc*L2c*HDc];
__device__ __align__(256) __half g_poolpl[(size_t)Bc*L2c*HDc];
__device__ __align__(256) __half g_poolsh[(size_t)Bc*L1c*HDc];
__device__ __align__(256) __half g_poolsl[(size_t)Bc*L1c*HDc];

// ---------------- helpers -----------------------------------------------------
__device__ __forceinline__ uint32_t smem_u32(const void* p) {
    uint32_t a;
    asm("{ .reg .u64 t; cvta.to.shared.u64 t, %1; cvt.u32.u64 %0, t; }" : "=r"(a) : "l"(p));
    return a;
}
__device__ __forceinline__ void cpa16(uint32_t dst, const void* src) {
    asm volatile("cp.async.cg.shared.global [%0], [%1], 16;" :: "r"(dst), "l"(src));
}
__device__ __forceinline__ void cpa_commit() { asm volatile("cp.async.commit_group;" ::: "memory"); }
__device__ __forceinline__ void cpa_wait0()  { asm volatile("cp.async.wait_group 0;" ::: "memory"); }

__device__ __forceinline__ void split2(float x, __half& h, __half& l) {
    h = __float2half_rn(x);
    l = __float2half_rn(x - __half2float(h));
}

#define CSLD 132   // f32 epilogue smem stride

// ---- staging: global fp16 rows -> smem tile (128 rows x KCH halves) ----------
// row stride = KCH+8 halves (bank-conflict-free for LDSM at both 40 and 72).
// MODE 0: G[(rb+m)*ld + k]    MODE 1: concat (k<Dc from G ld=Dc, else pool ld=HDc)
template<int KCH, int MODE>
__device__ __forceinline__ void stage16(const __half* __restrict__ G, int ld,
                                        const __half* __restrict__ pool,
                                        int rb, int k0, uint32_t dst) {
    constexpr int RPR = KCH / 8;          // cp.async per row
    constexpr int IT  = 128 * RPR / 256;  // per-thread iterations
    const int tid = threadIdx.x;
    #pragma unroll
    for (int r = 0; r < IT; r++) {
        int idx = r * 256 + tid;
        int m   = idx / RPR;
        int kq  = (idx % RPR) * 8;
        const __half* src;
        if (MODE == 0) {
            src = G + (size_t)(rb + m) * ld + k0 + kq;
        } else {
            int gk = k0 + kq;
            src = (gk < Dc) ? G    + (size_t)(rb + m) * Dc  + gk
                            : pool + (size_t)(rb + m) * HDc + (gk - Dc);
        }
        cpa16(dst + m * ((KCH + 8) * 2) + kq * 2, src);
    }
}

typedef wmma::fragment<wmma::matrix_a, 16, 16, 16, __half, wmma::row_major> FragA;
typedef wmma::fragment<wmma::matrix_b, 16, 16, 16, __half, wmma::col_major> FragB;
typedef wmma::fragment<wmma::accumulator, 16, 16, 16, float> FragC;

// ---------------- core GEMM ---------------------------------------------------
// C(128x128 tile) = A(MxK) x B(KxN). A,B given as fp16 hi/lo row-major-in-K.
// PASSES 3: AhBh+AlBh+AhBl (tiles Ah,Al,Bh,Bl). PASSES 2: AhBh+AlBh (no Bl).
// Pipeline: double-buffered, staging issued AFTER the per-chunk barrier
// (previous reader of the target buffer provably done) -> ONE sync per chunk.
// EPI 0: split-write hi/lo.  EPI 1: tanh*rs*cs -> aff h/l + affT h/l.
// EPI 2: relu -> f32.        EPI 3: relu(+bias) -> f32.
template<int PASSES, int KCH, int AMODE, int EPI>
__device__ __forceinline__ void gemm_core(
    const __half* __restrict__ Ah_g, const __half* __restrict__ Al_g,
    const __half* __restrict__ aph,  const __half* __restrict__ apl,
    const __half* __restrict__ Bh_g, const __half* __restrict__ Bl_g,
    float* __restrict__ Cf, __half* __restrict__ Ch, __half* __restrict__ Cl,
    __half* __restrict__ CTh, __half* __restrict__ CTl, int ldct,
    int K, int lda, int ldb, int ldc,
    const float* __restrict__ rs, const float* __restrict__ cs,
    const float* __restrict__ bias)
{
    constexpr int TLD   = KCH + 8;
    constexpr int TILEB = 128 * TLD * 2;
    constexpr int NT    = (PASSES == 3) ? 4 : 3;
    constexpr int BUFB  = NT * TILEB;

    extern __shared__ char smc[];
    const uint32_t smb = smem_u32(smc);

    const int tid  = threadIdx.x;
    const int wid  = tid >> 5;
    const int lane = tid & 31;
    const int wm   = wid & 3;
    const int wn   = wid >> 2;
    const int row0 = blockIdx.y * 128;
    const int col0 = blockIdx.x * 128;

    FragC acc[2][4];
    #pragma unroll
    for (int i = 0; i < 2; i++)
        #pragma unroll
        for (int j = 0; j < 4; j++) wmma::fill_fragment(acc[i][j], 0.0f);

    const int NCH = K / KCH;

    // prologue: stage chunk 0
    {
        stage16<KCH, AMODE>(Ah_g, lda, aph, row0, 0, smb);
        stage16<KCH, AMODE>(Al_g, lda, apl, row0, 0, smb + TILEB);
        stage16<KCH, 0>(Bh_g, ldb, nullptr, col0, 0, smb + 2 * TILEB);
        if (PASSES == 3)
            stage16<KCH, 0>(Bl_g, ldb, nullptr, col0, 0, smb + 3 * TILEB);
        cpa_commit();
    }

    for (int c = 0; c < NCH; c++) {
        cpa_wait0();         // chunk c landed (this thread's last group)
        __syncthreads();     // publish; also: all warps finished mma(c-1)
        if (c + 1 < NCH) {   // stage c+1 into the buffer mma(c-1) just vacated
            uint32_t nb = smb + ((c + 1) & 1) * BUFB;
            int k0 = (c + 1) * KCH;
            stage16<KCH, AMODE>(Ah_g, lda, aph, row0, k0, nb);
            stage16<KCH, AMODE>(Al_g, lda, apl, row0, k0, nb + TILEB);
            stage16<KCH, 0>(Bh_g, ldb, nullptr, col0, k0, nb + 2 * TILEB);
            if (PASSES == 3)
                stage16<KCH, 0>(Bl_g, ldb, nullptr, col0, k0, nb + 3 * TILEB);
            cpa_commit();
        } else {
            cpa_commit();    // empty group keeps wait_group accounting uniform
        }

        const __half* Ahs = (const __half*)(smc + (c & 1) * BUFB);
        const __half* Als = Ahs + TILEB / 2;
        const __half* Bhs = Ahs + TILEB;
        const __half* Bls = Ahs + 3 * (TILEB / 2);

        #pragma unroll
        for (int ks = 0; ks < KCH / 16; ks++) {
            FragA fah[2], fal[2];
            #pragma unroll
            for (int ti = 0; ti < 2; ti++) {
                int ro = (wm * 32 + ti * 16) * TLD + ks * 16;
                wmma::load_matrix_sync(fah[ti], Ahs + ro, TLD);
                wmma::load_matrix_sync(fal[ti], Als + ro, TLD);
            }
            #pragma unroll
            for (int tj = 0; tj < 4; tj++) {
                int co = (wn * 64 + tj * 16) * TLD + ks * 16;
                FragB fbh;
                wmma::load_matrix_sync(fbh, Bhs + co, TLD);
                #pragma unroll
                for (int ti = 0; ti < 2; ti++) {
                    wmma::mma_sync(acc[ti][tj], fah[ti], fbh, acc[ti][tj]);
                    wmma::mma_sync(acc[ti][tj], fal[ti], fbh, acc[ti][tj]);
                }
                if (PASSES == 3) {
                    FragB fbl;
                    wmma::load_matrix_sync(fbl, Bls + co, TLD);
                    #pragma unroll
                    for (int ti = 0; ti < 2; ti++)
                        wmma::mma_sync(acc[ti][tj], fah[ti], fbl, acc[ti][tj]);
                }
            }
        }
    }
    __syncthreads();   // all mma done before smem reuse by epilogue

    // ---------------- epilogue through smem -----------------------------------
    float* Cs = (float*)smc;
    #pragma unroll
    for (int ti = 0; ti < 2; ti++)
        #pragma unroll
        for (int tj = 0; tj < 4; tj++)
            wmma::store_matrix_sync(Cs + (wm * 32 + ti * 16) * CSLD + wn * 64 + tj * 16,
                                    acc[ti][tj], CSLD, wmma::mem_row_major);
    __syncthreads();

    #pragma unroll
    for (int it = 0; it < 16; it++) {
        int row = it * 8 + wid;
        float4 v = *(float4*)(Cs + row * CSLD + lane * 4);
        if (EPI == 0) {
            __half h0, h1, h2, h3, l0, l1, l2, l3;
            split2(v.x, h0, l0); split2(v.y, h1, l1);
            split2(v.z, h2, l2); split2(v.w, h3, l3);
            size_t off = (size_t)(row0 + row) * ldc + col0 + lane * 4;
            *(__half2*)(Ch + off)     = __halves2half2(h0, h1);
            *(__half2*)(Ch + off + 2) = __halves2half2(h2, h3);
            *(__half2*)(Cl + off)     = __halves2half2(l0, l1);
            *(__half2*)(Cl + off + 2) = __halves2half2(l2, l3);
        } else if (EPI == 1) {
            float rm = rs[row0 + row];
            v.x = tanhf(v.x) * rm * cs[col0 + lane * 4 + 0];
            v.y = tanhf(v.y) * rm * cs[col0 + lane * 4 + 1];
            v.z = tanhf(v.z) * rm * cs[col0 + lane * 4 + 2];
            v.w = tanhf(v.w) * rm * cs[col0 + lane * 4 + 3];
            *(float4*)(Cs + row * CSLD + lane * 4) = v;   // for transposed pass
            __half h0, h1, h2, h3, l0, l1, l2, l3;
            split2(v.x, h0, l0); split2(v.y, h1, l1);
            split2(v.z, h2, l2); split2(v.w, h3, l3);
            size_t off = (size_t)(row0 + row) * ldc + col0 + lane * 4;
            *(__half2*)(Ch + off)     = __halves2half2(h0, h1);
            *(__half2*)(Ch + off + 2) = __halves2half2(h2, h3);
            *(__half2*)(Cl + off)     = __halves2half2(l0, l1);
            *(__half2*)(Cl + off + 2) = __halves2half2(l2, l3);
        } else if (EPI == 2) {
            v.x = fmaxf(v.x, 0.f); v.y = fmaxf(v.y, 0.f);
            v.z = fmaxf(v.z, 0.f); v.w = fmaxf(v.w, 0.f);
            *(float4*)(Cf + (size_t)(row0 + row) * ldc + col0 + lane * 4) = v;
        } else {
            v.x = fmaxf(v.x + bias[col0 + lane * 4 + 0], 0.f);
            v.y = fmaxf(v.y + bias[col0 + lane * 4 + 1], 0.f);
            v.z = fmaxf(v.z + bias[col0 + lane * 4 + 2], 0.f);
            v.w = fmaxf(v.w + bias[col0 + lane * 4 + 3], 0.f);
            *(float4*)(Cf + (size_t)(row0 + row) * ldc + col0 + lane * 4) = v;
        }
    }

    if (EPI == 1) {
        __syncthreads();
        #pragma unroll
        for (int ct = 0; ct < 16; ct++) {
            int col = ct * 8 + wid;
            #pragma unroll
            for (int cc = 0; cc < 4; cc++) {
                int r = cc * 32 + lane;
                float x = Cs[r * CSLD + col];
                __half h, l;
                split2(x, h, l);
                size_t off = (size_t)(col0 + col) * ldct + row0 + r;
                CTh[off] = h;
                CTl[off] = l;
            }
        }
    }
}

// smem sizes
#define SM_P3 (2 * 4 * (128 * 40 * 2))   // 81920  (3-pass, KCH=32)
#define SM_P2 (2 * 3 * (128 * 72 * 2))   // 110592 (2-pass, KCH=64)

// ---------------- GEMM kernels ------------------------------------------------
__global__ __launch_bounds__(256, 2) void k_pw() {
    int bh = blockIdx.z;
    gemm_core<3, 32, 0, 0>(g_Ph + (size_t)(bh >> 3) * L1c * Dc,
                           g_Pl + (size_t)(bh >> 3) * L1c * Dc, nullptr, nullptr,
                           g_WaffTh + (size_t)(bh & 7) * Dc * Dc,
                           g_WaffTl + (size_t)(bh & 7) * Dc * Dc,
                           nullptr, g_Th + (size_t)bh * L1c * Dc,
                           g_Tl + (size_t)bh * L1c * Dc,
                           nullptr, nullptr, 0,
                           Dc, Dc, Dc, Dc, nullptr, nullptr, nullptr);
}
__global__ __launch_bounds__(256, 2) void k_aff(const float* __restrict__ pm,
                                                const float* __restrict__ sm_) {
    int bh = blockIdx.z, b = bh >> 3;
    gemm_core<3, 32, 0, 1>(g_Th + (size_t)bh * L1c * Dc,
                           g_Tl + (size_t)bh * L1c * Dc, nullptr, nullptr,
                           g_Sh + (size_t)b * L2c * Dc,
                           g_Sl + (size_t)b * L2c * Dc,
                           nullptr,
                           g_affh + (size_t)bh * L1c * L2c,
                           g_affl + (size_t)bh * L1c * L2c,
                           g_affTh + (size_t)bh * L2c * L1c,
                           g_affTl + (size_t)bh * L2c * L1c, L1c,
                           Dc, Dc, Dc, L2c,
                           pm + b * L1c, sm_ + b * L2c, nullptr);
}
__global__ __launch_bounds__(256, 2) void k_projP() {
    int b = blockIdx.z;
    gemm_core<2, 64, 0, 0>(g_WpTh, g_WpTl, nullptr, nullptr,
                           g_Ph + (size_t)b * L1c * Dc, g_Pl + (size_t)b * L1c * Dc,
                           nullptr,
                           g_PPTh + (size_t)b * INNERc * L1c,
                           g_PPTl + (size_t)b * INNERc * L1c,
                           nullptr, nullptr, 0,
                           Dc, Dc, Dc, L1c, nullptr, nullptr, nullptr);
}
__global__ __launch_bounds__(256, 2) void k_projS() {
    int b = blockIdx.z;
    gemm_core<2, 64, 0, 0>(g_WsTh, g_WsTl, nullptr, nullptr,
                           g_Sh + (size_t)b * L2c * Dc, g_Sl + (size_t)b * L2c * Dc,
                           nullptr,
                           g_PSTh + (size_t)b * INNERc * L2c,
                           g_PSTl + (size_t)b * INNERc * L2c,
                           nullptr, nullptr, 0,
                           Dc, Dc, Dc, L2c, nullptr, nullptr, nullptr);
}
__global__ __launch_bounds__(256, 2) void k_wp() {
    int bh = blockIdx.z, b = bh >> 3, h = bh & 7;
    gemm_core<2, 64, 0, 2>(g_affTh + (size_t)bh * L2c * L1c,
                           g_affTl + (size_t)bh * L2c * L1c, nullptr, nullptr,
                           g_PPTh + (size_t)b * INNERc * L1c + (size_t)h * HDc * L1c,
                           g_PPTl + (size_t)b * INNERc * L1c + (size_t)h * HDc * L1c,
                           g_wp + (size_t)bh * L2c * HDc, nullptr, nullptr,
                           nullptr, nullptr, 0,
                           L1c, L1c, L1c, HDc, nullptr, nullptr, nullptr);
}
__global__ __launch_bounds__(256, 2) void k_ws() {
    int bh = blockIdx.z, b = bh >> 3, h = bh & 7;
    gemm_core<2, 64, 0, 2>(g_affh + (size_t)bh * L1c * L2c,
                           g_affl + (size_t)bh * L1c * L2c, nullptr, nullptr,
                           g_PSTh + (size_t)b * INNERc * L2c + (size_t)h * HDc * L2c,
                           g_PSTl + (size_t)b * INNERc * L2c + (size_t)h * HDc * L2c,
                           g_ws + (size_t)bh * L1c * HDc, nullptr, nullptr,
                           nullptr, nullptr, 0,
                           L2c, L2c, L2c, HDc, nullptr, nullptr, nullptr);
}
__global__ __launch_bounds__(256, 2) void k_ffnp(const float* __restrict__ bias,
                                                 float* __restrict__ O) {
    int b = blockIdx.z;
    gemm_core<2, 64, 1, 3>(g_Ph + (size_t)b * L1c * Dc, g_Pl + (size_t)b * L1c * Dc,
                           g_poolsh + (size_t)b * L1c * HDc,
                           g_poolsl + (size_t)b * L1c * HDc,
                           g_WfpTh, g_WfpTl,
                           O + (size_t)b * L1c * Dc, nullptr, nullptr,
                           nullptr, nullptr, 0,
                           DCc, Dc, DCc, Dc, nullptr, nullptr, bias);
}
__global__ __launch_bounds__(256, 2) void k_ffns(const float* __restrict__ bias,
                                                 float* __restrict__ O) {
    int b = blockIdx.z;
    gemm_core<2, 64, 1, 3>(g_Sh + (size_t)b * L2c * Dc, g_Sl + (size_t)b * L2c * Dc,
                           g_poolph + (size_t)b * L2c * HDc,
                           g_poolpl + (size_t)b * L2c * HDc,
                           g_WfsTh, g_WfsTl,
                           O + (size_t)b * L2c * Dc, nullptr, nullptr,
                           nullptr, nullptr, 0,
                           DCc, Dc, DCc, Dc, nullptr, nullptr, bias);
}

// ---------------- conversion kernels ------------------------------------------
__global__ void k_split(const float* __restrict__ X,
                        __half* __restrict__ H, __half* __restrict__ L, int n) {
    int i = (blockIdx.x * blockDim.x + threadIdx.x) * 4;
    if (i >= n) return;
    float4 v = *(const float4*)(X + i);
    __half h0, h1, h2, h3, l0, l1, l2, l3;
    split2(v.x, h0, l0); split2(v.y, h1, l1);
    split2(v.z, h2, l2); split2(v.w, h3, l3);
    *(__half2*)(H + i)     = __halves2half2(h0, h1);
    *(__half2*)(H + i + 2) = __halves2half2(h2, h3);
    *(__half2*)(L + i)     = __halves2half2(l0, l1);
    *(__half2*)(L + i + 2) = __halves2half2(l2, l3);
}

// transpose + split: X[z][R][C] f32 -> H/L [z][C][R] fp16
__global__ void k_splitT(const float* __restrict__ X,
                         __half* __restrict__ H, __half* __restrict__ L,
                         int R, int C) {
    __shared__ float t[32][33];
    int z = blockIdx.z;
    int x0 = blockIdx.x * 32;
    int y0 = blockIdx.y * 32;
    const float* Xz = X + (size_t)z * R * C;
    #pragma unroll
    for (int i = 0; i < 4; i++) {
        int r = y0 + threadIdx.y * 4 + i;
        t[threadIdx.y * 4 + i][threadIdx.x] = Xz[(size_t)r * C + x0 + threadIdx.x];
    }
    __syncthreads();
    size_t zb = (size_t)z * R * C;
    #pragma unroll
    for (int i = 0; i < 4; i++) {
        int oc = x0 + threadIdx.y * 4 + i;
        float v = t[threadIdx.x][threadIdx.y * 4 + i];
        __half h, l;
        split2(v, h, l);
        H[zb + (size_t)oc * R + y0 + threadIdx.x] = h;
        L[zb + (size_t)oc * R + y0 + threadIdx.x] = l;
    }
}

// paired variant: z selects between two (src,dst) pairs — fewer launches so ncu's
// skip-5 capture lands on k_pw.
__global__ void k_splitT2(const float* __restrict__ X0, __half* __restrict__ H0, __half* __restrict__ L0,
                          const float* __restrict__ X1, __half* __restrict__ H1, __half* __restrict__ L1,
                          int R, int C) {
    __shared__ float t[32][33];
    int pair = blockIdx.z;
    const float* X = pair ? X1 : X0;
    __half* H = pair ? H1 : H0;
    __half* L = pair ? L1 : L0;
    int x0 = blockIdx.x * 32;
    int y0 = blockIdx.y * 32;
    #pragma unroll
    for (int i = 0; i < 4; i++) {
        int r = y0 + threadIdx.y * 4 + i;
        t[threadIdx.y * 4 + i][threadIdx.x] = X[(size_t)r * C + x0 + threadIdx.x];
    }
    __syncthreads();
    #pragma unroll
    for (int i = 0; i < 4; i++) {
        int oc = x0 + threadIdx.y * 4 + i;
        float v = t[threadIdx.x][threadIdx.y * 4 + i];
        __half h, l;
        split2(v, h, l);
        H[(size_t)oc * R + y0 + threadIdx.x] = h;
        L[(size_t)oc * R + y0 + threadIdx.x] = l;
    }
}

// ---------------- pools --------------------------------------------------------
__global__ void k_poolp() {
    int idx = blockIdx.x * blockDim.x + threadIdx.x;
    const int tot = Bc * L2c * HDc;
    if (idx >= tot) return;
    int b = idx / (L2c * HDc);
    int r = idx - b * (L2c * HDc);
    float m = g_wp[((size_t)b * Hc) * L2c * HDc + r];
    #pragma unroll
    for (int h = 1; h < Hc; h++)
        m = fmaxf(m, g_wp[((size_t)(b * Hc + h)) * L2c * HDc + r]);
    __half hh, ll;
    split2(m, hh, ll);
    g_poolph[idx] = hh;
    g_poolpl[idx] = ll;
}
__global__ void k_pools() {
    int idx = blockIdx.x * blockDim.x + threadIdx.x;
    const int tot = Bc * L1c * HDc;
    if (idx >= tot) return;
    int b = idx / (L1c * HDc);
    int r = idx - b * (L1c * HDc);
    float m = g_ws[((size_t)b * Hc) * L1c * HDc + r];
    #pragma unroll
    for (int h = 1; h < Hc; h++)
        m = fmaxf(m, g_ws[((size_t)(b * Hc + h)) * L1c * HDc + r]);
    __half hh, ll;
    split2(m, hh, ll);
    g_poolsh[idx] = hh;
    g_poolsl[idx] = ll;
}

// ---------------- launcher -----------------------------------------------------
template<typename T>
static T* sym_addr(const void* sym) {
    void* p = nullptr;
    cudaGetSymbolAddress(&p, sym);     // host-side query: capture-safe, no alloc
    return (T*)p;
}

extern "C" void kernel_launch(void* const* d_in, const int* in_sizes, int n_in,
                              void* d_out, int out_size) {
    const float* P    = (const float*)d_in[0];
    const float* S    = (const float*)d_in[1];
    const float* pm   = (const float*)d_in[2];
    const float* sm   = (const float*)d_in[3];
    const float* Waff = (const float*)d_in[4];
    const float* Wp   = (const float*)d_in[5];
    const float* Ws   = (const float*)d_in[6];
    const float* Wfp  = (const float*)d_in[7];
    const float* bfp  = (const float*)d_in[8];
    const float* Wfs  = (const float*)d_in[9];
    const float* bfs  = (const float*)d_in[10];

    float* outp = (float*)d_out;
    float* outs = outp + (size_t)Bc * L1c * Dc;

    __half* Ph     = sym_addr<__half>(g_Ph);
    __half* Pl     = sym_addr<__half>(g_Pl);
    __half* Sh     = sym_addr<__half>(g_Sh);
    __half* Sl     = sym_addr<__half>(g_Sl);
    __half* WaffTh = sym_addr<__half>(g_WaffTh);
    __half* WaffTl = sym_addr<__half>(g_WaffTl);
    __half* WpTh   = sym_addr<__half>(g_WpTh);
    __half* WpTl   = sym_addr<__half>(g_WpTl);
    __half* WsTh   = sym_addr<__half>(g_WsTh);
    __half* WsTl   = sym_addr<__half>(g_WsTl);
    __half* WfpTh  = sym_addr<__half>(g_WfpTh);
    __half* WfpTl  = sym_addr<__half>(g_WfpTl);
    __half* WfsTh  = sym_addr<__half>(g_WfsTh);
    __half* WfsTl  = sym_addr<__half>(g_WfsTl);

    cudaFuncSetAttribute(k_pw,    cudaFuncAttributeMaxDynamicSharedMemorySize, SM_P3);
    cudaFuncSetAttribute(k_aff,   cudaFuncAttributeMaxDynamicSharedMemorySize, SM_P3);
    cudaFuncSetAttribute(k_projP, cudaFuncAttributeMaxDynamicSharedMemorySize, SM_P2);
    cudaFuncSetAttribute(k_projS, cudaFuncAttributeMaxDynamicSharedMemorySize, SM_P2);
    cudaFuncSetAttribute(k_wp,    cudaFuncAttributeMaxDynamicSharedMemorySize, SM_P2);
    cudaFuncSetAttribute(k_ws,    cudaFuncAttributeMaxDynamicSharedMemorySize, SM_P2);
    cudaFuncSetAttribute(k_ffnp,  cudaFuncAttributeMaxDynamicSharedMemorySize, SM_P2);
    cudaFuncSetAttribute(k_ffns,  cudaFuncAttributeMaxDynamicSharedMemorySize, SM_P2);

    // conversions — exactly 5 launches so ncu (-s 5 -c 1) captures k_pw next
    {
        int n = Bc * L1c * Dc;
        k_split<<<n / 1024, 256>>>(P, Ph, Pl, n);
        k_split<<<n / 1024, 256>>>(S, Sh, Sl, n);
    }
    k_splitT<<<dim3(Dc / 32, Dc / 32, Hc), dim3(32, 8)>>>(Waff, WaffTh, WaffTl, Dc, Dc);
    k_splitT2<<<dim3(INNERc / 32, Dc / 32, 2), dim3(32, 8)>>>(Wp, WpTh, WpTl,
                                                              Ws, WsTh, WsTl, Dc, INNERc);
    k_splitT2<<<dim3(Dc / 32, DCc / 32, 2), dim3(32, 8)>>>(Wfp, WfpTh, WfpTl,
                                                           Wfs, WfsTh, WfsTl, DCc, Dc);

    dim3 blk(256);

    k_pw   <<<dim3(4, 4, Bc * Hc), blk, SM_P3>>>();
    k_aff  <<<dim3(4, 4, Bc * Hc), blk, SM_P3>>>(pm, sm);
    k_projP<<<dim3(4, 8, Bc),      blk, SM_P2>>>();
    k_projS<<<dim3(4, 8, Bc),      blk, SM_P2>>>();
    k_wp   <<<dim3(1, 4, Bc * Hc), blk, SM_P2>>>();
    k_ws   <<<dim3(1, 4, Bc * Hc), blk, SM_P2>>>();

    { int tot = Bc * L2c * HDc; k_poolp<<<(tot + 255) / 256, 256>>>(); }
    { int tot = Bc * L1c * HDc; k_pools<<<(tot + 255) / 256, 256>>>(); }

    k_ffnp <<<dim3(4, 4, Bc), blk, SM_P2>>>(bfp, outp);
    k_ffns <<<dim3(4, 4, Bc), blk, SM_P2>>>(bfs, outs);
}

// round 8
// speedup vs baseline: 4.3628x; 1.0385x over previous
#include <cuda_runtime.h>
#include <cuda_fp16.h>
#include <mma.h>
#include <math.h>
#include <stdint.h>

using namespace nvcuda;

// Problem constants
#define Bc     16
#define L1c    512
#define L2c    512
#define Dc     512
#define Hc     8
#define INNERc 1024
#define HDc    128
#define DCc    640   // D + HD

// ---------------- fp16 hi/lo pair scratch (static device globals) -------------
__device__ __align__(256) __half g_Ph [(size_t)Bc*L1c*Dc];
__device__ __align__(256) __half g_Pl [(size_t)Bc*L1c*Dc];
__device__ __align__(256) __half g_Sh [(size_t)Bc*L2c*Dc];
__device__ __align__(256) __half g_Sl [(size_t)Bc*L2c*Dc];
__device__ __align__(256) __half g_WaffTh[(size_t)Hc*Dc*Dc];
__device__ __align__(256) __half g_WaffTl[(size_t)Hc*Dc*Dc];
__device__ __align__(256) __half g_WpTh[(size_t)INNERc*Dc];
__device__ __align__(256) __half g_WpTl[(size_t)INNERc*Dc];
__device__ __align__(256) __half g_WsTh[(size_t)INNERc*Dc];
__device__ __align__(256) __half g_WsTl[(size_t)INNERc*Dc];
__device__ __align__(256) __half g_WfpTh[(size_t)Dc*DCc];
__device__ __align__(256) __half g_WfpTl[(size_t)Dc*DCc];
__device__ __align__(256) __half g_WfsTh[(size_t)Dc*DCc];
__device__ __align__(256) __half g_WfsTl[(size_t)Dc*DCc];
__device__ __align__(256) __half g_Th  [(size_t)Bc*Hc*L1c*Dc];
__device__ __align__(256) __half g_Tl  [(size_t)Bc*Hc*L1c*Dc];
__device__ __align__(256) __half g_affh [(size_t)Bc*Hc*L1c*L2c];
__device__ __align__(256) __half g_affl [(size_t)Bc*Hc*L1c*L2c];
__device__ __align__(256) __half g_affTh[(size_t)Bc*Hc*L2c*L1c];
__device__ __align__(256) __half g_affTl[(size_t)Bc*Hc*L2c*L1c];
__device__ __align__(256) __half g_PPTh[(size_t)Bc*INNERc*L1c];
__device__ __align__(256) __half g_PPTl[(size_t)Bc*INNERc*L1c];
__device__ __align__(256) __half g_PSTh[(size_t)Bc*INNERc*L2c];
__device__ __align__(256) __half g_PSTl[(size_t)Bc*INNERc*L2c];
__device__ __align__(256) float  g_wp [(size_t)Bc*Hc*L2c*HDc];
__device__ __align__(256) float  g_ws [(size_t)Bc*Hc*L1c*HDc];
__device__ __align__(256) __half g_poolph[(size_t)Bc*L2c*HDc];
__device__ __align__(256) __half g_poolpl[(size_t)Bc*L2c*HDc];
__device__ __align__(256) __half g_poolsh[(size_t)Bc*L1c*HDc];
__device__ __align__(256) __half g_poolsl[(size_t)Bc*L1c*HDc];

// ---------------- helpers -----------------------------------------------------
__device__ __forceinline__ uint32_t smem_u32(const void* p) {
    uint32_t a;
    asm("{ .reg .u64 t; cvta.to.shared.u64 t, %1; cvt.u32.u64 %0, t; }" : "=r"(a) : "l"(p));
    return a;
}
__device__ __forceinline__ void cpa16(uint32_t dst, const void* src) {
    asm volatile("cp.async.cg.shared.global [%0], [%1], 16;" :: "r"(dst), "l"(src));
}
__device__ __forceinline__ void cpa_commit() { asm volatile("cp.async.commit_group;" ::: "memory"); }
__device__ __forceinline__ void cpa_wait0()  { asm volatile("cp.async.wait_group 0;" ::: "memory"); }

__device__ __forceinline__ void split2(float x, __half& h, __half& l) {
    h = __float2half_rn(x);
    l = __float2half_rn(x - __half2float(h));
}

#define CSLD 132   // f32 epilogue smem stride

// ---- staging: global fp16 rows -> smem tile (128 rows x KCH halves) ----------
template<int KCH, int MODE>
__device__ __forceinline__ void stage16(const __half* __restrict__ G, int ld,
                                        const __half* __restrict__ pool,
                                        int rb, int k0, uint32_t dst) {
    constexpr int RPR = KCH / 8;
    constexpr int IT  = 128 * RPR / 256;
    const int tid = threadIdx.x;
    #pragma unroll
    for (int r = 0; r < IT; r++) {
        int idx = r * 256 + tid;
        int m   = idx / RPR;
        int kq  = (idx % RPR) * 8;
        const __half* src;
        if (MODE == 0) {
            src = G + (size_t)(rb + m) * ld + k0 + kq;
        } else {
            int gk = k0 + kq;
            src = (gk < Dc) ? G    + (size_t)(rb + m) * Dc  + gk
                            : pool + (size_t)(rb + m) * HDc + (gk - Dc);
        }
        cpa16(dst + m * ((KCH + 8) * 2) + kq * 2, src);
    }
}

typedef wmma::fragment<wmma::matrix_a, 16, 16, 16, __half, wmma::row_major> FragA;
typedef wmma::fragment<wmma::matrix_b, 16, 16, 16, __half, wmma::col_major> FragB;
typedef wmma::fragment<wmma::accumulator, 16, 16, 16, float> FragC;

// ---------------- core GEMM (identical math to round 7) -----------------------
template<int PASSES, int KCH, int AMODE, int EPI>
__device__ __forceinline__ void gemm_core(
    const __half* __restrict__ Ah_g, const __half* __restrict__ Al_g,
    const __half* __restrict__ aph,  const __half* __restrict__ apl,
    const __half* __restrict__ Bh_g, const __half* __restrict__ Bl_g,
    float* __restrict__ Cf, __half* __restrict__ Ch, __half* __restrict__ Cl,
    __half* __restrict__ CTh, __half* __restrict__ CTl, int ldct,
    int K, int lda, int ldb, int ldc,
    const float* __restrict__ rs, const float* __restrict__ cs,
    const float* __restrict__ bias)
{
    constexpr int TLD   = KCH + 8;
    constexpr int TILEB = 128 * TLD * 2;
    constexpr int NT    = (PASSES == 3) ? 4 : 3;
    constexpr int BUFB  = NT * TILEB;

    extern __shared__ char smc[];
    const uint32_t smb = smem_u32(smc);

    const int tid  = threadIdx.x;
    const int wid  = tid >> 5;
    const int lane = tid & 31;
    const int wm   = wid & 3;
    const int wn   = wid >> 2;
    const int row0 = blockIdx.y * 128;
    const int col0 = blockIdx.x * 128;

    FragC acc[2][4];
    #pragma unroll
    for (int i = 0; i < 2; i++)
        #pragma unroll
        for (int j = 0; j < 4; j++) wmma::fill_fragment(acc[i][j], 0.0f);

    const int NCH = K / KCH;

    {
        stage16<KCH, AMODE>(Ah_g, lda, aph, row0, 0, smb);
        stage16<KCH, AMODE>(Al_g, lda, apl, row0, 0, smb + TILEB);
        stage16<KCH, 0>(Bh_g, ldb, nullptr, col0, 0, smb + 2 * TILEB);
        if (PASSES == 3)
            stage16<KCH, 0>(Bl_g, ldb, nullptr, col0, 0, smb + 3 * TILEB);
        cpa_commit();
    }

    for (int c = 0; c < NCH; c++) {
        cpa_wait0();
        __syncthreads();
        if (c + 1 < NCH) {
            uint32_t nb = smb + ((c + 1) & 1) * BUFB;
            int k0 = (c + 1) * KCH;
            stage16<KCH, AMODE>(Ah_g, lda, aph, row0, k0, nb);
            stage16<KCH, AMODE>(Al_g, lda, apl, row0, k0, nb + TILEB);
            stage16<KCH, 0>(Bh_g, ldb, nullptr, col0, k0, nb + 2 * TILEB);
            if (PASSES == 3)
                stage16<KCH, 0>(Bl_g, ldb, nullptr, col0, k0, nb + 3 * TILEB);
            cpa_commit();
        } else {
            cpa_commit();
        }

        const __half* Ahs = (const __half*)(smc + (c & 1) * BUFB);
        const __half* Als = Ahs + TILEB / 2;
        const __half* Bhs = Ahs + TILEB;
        const __half* Bls = Ahs + 3 * (TILEB / 2);

        #pragma unroll
        for (int ks = 0; ks < KCH / 16; ks++) {
            FragA fah[2], fal[2];
            #pragma unroll
            for (int ti = 0; ti < 2; ti++) {
                int ro = (wm * 32 + ti * 16) * TLD + ks * 16;
                wmma::load_matrix_sync(fah[ti], Ahs + ro, TLD);
                wmma::load_matrix_sync(fal[ti], Als + ro, TLD);
            }
            #pragma unroll
            for (int tj = 0; tj < 4; tj++) {
                int co = (wn * 64 + tj * 16) * TLD + ks * 16;
                FragB fbh;
                wmma::load_matrix_sync(fbh, Bhs + co, TLD);
                #pragma unroll
                for (int ti = 0; ti < 2; ti++) {
                    wmma::mma_sync(acc[ti][tj], fah[ti], fbh, acc[ti][tj]);
                    wmma::mma_sync(acc[ti][tj], fal[ti], fbh, acc[ti][tj]);
                }
                if (PASSES == 3) {
                    FragB fbl;
                    wmma::load_matrix_sync(fbl, Bls + co, TLD);
                    #pragma unroll
                    for (int ti = 0; ti < 2; ti++)
                        wmma::mma_sync(acc[ti][tj], fah[ti], fbl, acc[ti][tj]);
                }
            }
        }
    }
    __syncthreads();

    // ---------------- epilogue through smem -----------------------------------
    float* Cs = (float*)smc;
    #pragma unroll
    for (int ti = 0; ti < 2; ti++)
        #pragma unroll
        for (int tj = 0; tj < 4; tj++)
            wmma::store_matrix_sync(Cs + (wm * 32 + ti * 16) * CSLD + wn * 64 + tj * 16,
                                    acc[ti][tj], CSLD, wmma::mem_row_major);
    __syncthreads();

    #pragma unroll
    for (int it = 0; it < 16; it++) {
        int row = it * 8 + wid;
        float4 v = *(float4*)(Cs + row * CSLD + lane * 4);
        if (EPI == 0) {
            __half h0, h1, h2, h3, l0, l1, l2, l3;
            split2(v.x, h0, l0); split2(v.y, h1, l1);
            split2(v.z, h2, l2); split2(v.w, h3, l3);
            size_t off = (size_t)(row0 + row) * ldc + col0 + lane * 4;
            *(__half2*)(Ch + off)     = __halves2half2(h0, h1);
            *(__half2*)(Ch + off + 2) = __halves2half2(h2, h3);
            *(__half2*)(Cl + off)     = __halves2half2(l0, l1);
            *(__half2*)(Cl + off + 2) = __halves2half2(l2, l3);
        } else if (EPI == 1) {
            float rm = rs[row0 + row];
            v.x = tanhf(v.x) * rm * cs[col0 + lane * 4 + 0];
            v.y = tanhf(v.y) * rm * cs[col0 + lane * 4 + 1];
            v.z = tanhf(v.z) * rm * cs[col0 + lane * 4 + 2];
            v.w = tanhf(v.w) * rm * cs[col0 + lane * 4 + 3];
            *(float4*)(Cs + row * CSLD + lane * 4) = v;
            __half h0, h1, h2, h3, l0, l1, l2, l3;
            split2(v.x, h0, l0); split2(v.y, h1, l1);
            split2(v.z, h2, l2); split2(v.w, h3, l3);
            size_t off = (size_t)(row0 + row) * ldc + col0 + lane * 4;
            *(__half2*)(Ch + off)     = __halves2half2(h0, h1);
            *(__half2*)(Ch + off + 2) = __halves2half2(h2, h3);
            *(__half2*)(Cl + off)     = __halves2half2(l0, l1);
            *(__half2*)(Cl + off + 2) = __halves2half2(l2, l3);
        } else if (EPI == 2) {
            v.x = fmaxf(v.x, 0.f); v.y = fmaxf(v.y, 0.f);
            v.z = fmaxf(v.z, 0.f); v.w = fmaxf(v.w, 0.f);
            *(float4*)(Cf + (size_t)(row0 + row) * ldc + col0 + lane * 4) = v;
        } else {
            v.x = fmaxf(v.x + bias[col0 + lane * 4 + 0], 0.f);
            v.y = fmaxf(v.y + bias[col0 + lane * 4 + 1], 0.f);
            v.z = fmaxf(v.z + bias[col0 + lane * 4 + 2], 0.f);
            v.w = fmaxf(v.w + bias[col0 + lane * 4 + 3], 0.f);
            *(float4*)(Cf + (size_t)(row0 + row) * ldc + col0 + lane * 4) = v;
        }
    }

    if (EPI == 1) {
        __syncthreads();
        #pragma unroll
        for (int ct = 0; ct < 16; ct++) {
            int col = ct * 8 + wid;
            #pragma unroll
            for (int cc = 0; cc < 4; cc++) {
                int r = cc * 32 + lane;
                float x = Cs[r * CSLD + col];
                __half h, l;
                split2(x, h, l);
                size_t off = (size_t)(col0 + col) * ldct + row0 + r;
                CTh[off] = h;
                CTl[off] = l;
            }
        }
    }
}

// smem sizes
#define SM_P3 (2 * 4 * (128 * 40 * 2))   // 81920  (3-pass, KCH=32)
#define SM_P2 (2 * 3 * (128 * 72 * 2))   // 110592 (2-pass, KCH=64)

// ---------------- GEMM kernels ------------------------------------------------
__global__ __launch_bounds__(256, 2) void k_pw() {
    int bh = blockIdx.z;
    gemm_core<3, 32, 0, 0>(g_Ph + (size_t)(bh >> 3) * L1c * Dc,
                           g_Pl + (size_t)(bh >> 3) * L1c * Dc, nullptr, nullptr,
                           g_WaffTh + (size_t)(bh & 7) * Dc * Dc,
                           g_WaffTl + (size_t)(bh & 7) * Dc * Dc,
                           nullptr, g_Th + (size_t)bh * L1c * Dc,
                           g_Tl + (size_t)bh * L1c * Dc,
                           nullptr, nullptr, 0,
                           Dc, Dc, Dc, Dc, nullptr, nullptr, nullptr);
}
__global__ __launch_bounds__(256, 2) void k_aff(const float* __restrict__ pm,
                                                const float* __restrict__ sm_) {
    int bh = blockIdx.z, b = bh >> 3;
    gemm_core<3, 32, 0, 1>(g_Th + (size_t)bh * L1c * Dc,
                           g_Tl + (size_t)bh * L1c * Dc, nullptr, nullptr,
                           g_Sh + (size_t)b * L2c * Dc,
                           g_Sl + (size_t)b * L2c * Dc,
                           nullptr,
                           g_affh + (size_t)bh * L1c * L2c,
                           g_affl + (size_t)bh * L1c * L2c,
                           g_affTh + (size_t)bh * L2c * L1c,
                           g_affTl + (size_t)bh * L2c * L1c, L1c,
                           Dc, Dc, Dc, L2c,
                           pm + b * L1c, sm_ + b * L2c, nullptr);
}
// merged projP+projS: z = b*2 + sel
__global__ __launch_bounds__(256, 2) void k_proj() {
    int b = blockIdx.z >> 1, sel = blockIdx.z & 1;
    const __half* Wh = sel ? g_WsTh : g_WpTh;
    const __half* Wl = sel ? g_WsTl : g_WpTl;
    const __half* Xh = (sel ? g_Sh : g_Ph) + (size_t)b * L1c * Dc;
    const __half* Xl = (sel ? g_Sl : g_Pl) + (size_t)b * L1c * Dc;
    __half* Oh = (sel ? g_PSTh : g_PPTh) + (size_t)b * INNERc * L1c;
    __half* Ol = (sel ? g_PSTl : g_PPTl) + (size_t)b * INNERc * L1c;
    gemm_core<2, 64, 0, 0>(Wh, Wl, nullptr, nullptr, Xh, Xl,
                           nullptr, Oh, Ol, nullptr, nullptr, 0,
                           Dc, Dc, Dc, L1c, nullptr, nullptr, nullptr);
}
// merged wp+ws: z = bh*2 + sel
__global__ __launch_bounds__(256, 2) void k_wpws() {
    int bh = blockIdx.z >> 1, sel = blockIdx.z & 1;
    int b = bh >> 3, h = bh & 7;
    const __half *Ah_, *Al_, *Bh_, *Bl_;
    float* Cf;
    if (sel == 0) {   // wp
        Ah_ = g_affTh + (size_t)bh * L2c * L1c;
        Al_ = g_affTl + (size_t)bh * L2c * L1c;
        Bh_ = g_PPTh + (size_t)b * INNERc * L1c + (size_t)h * HDc * L1c;
        Bl_ = g_PPTl + (size_t)b * INNERc * L1c + (size_t)h * HDc * L1c;
        Cf  = g_wp + (size_t)bh * L2c * HDc;
    } else {          // ws
        Ah_ = g_affh + (size_t)bh * L1c * L2c;
        Al_ = g_affl + (size_t)bh * L1c * L2c;
        Bh_ = g_PSTh + (size_t)b * INNERc * L2c + (size_t)h * HDc * L2c;
        Bl_ = g_PSTl + (size_t)b * INNERc * L2c + (size_t)h * HDc * L2c;
        Cf  = g_ws + (size_t)bh * L1c * HDc;
    }
    gemm_core<2, 64, 0, 2>(Ah_, Al_, nullptr, nullptr, Bh_, Bl_,
                           Cf, nullptr, nullptr, nullptr, nullptr, 0,
                           L1c, L1c, L1c, HDc, nullptr, nullptr, nullptr);
}
// merged ffnp+ffns: z = b*2 + sel
__global__ __launch_bounds__(256, 2) void k_ffn(const float* __restrict__ bfp,
                                                const float* __restrict__ bfs,
                                                float* __restrict__ Op,
                                                float* __restrict__ Os) {
    int b = blockIdx.z >> 1, sel = blockIdx.z & 1;
    const __half* Xh = (sel ? g_Sh : g_Ph) + (size_t)b * L1c * Dc;
    const __half* Xl = (sel ? g_Sl : g_Pl) + (size_t)b * L1c * Dc;
    const __half* ph = (sel ? g_poolph : g_poolsh) + (size_t)b * L1c * HDc;
    const __half* pl = (sel ? g_poolpl : g_poolsl) + (size_t)b * L1c * HDc;
    const __half* Wh = sel ? g_WfsTh : g_WfpTh;
    const __half* Wl = sel ? g_WfsTl : g_WfpTl;
    const float* bias = sel ? bfs : bfp;
    float* O = (sel ? Os : Op) + (size_t)b * L1c * Dc;
    gemm_core<2, 64, 1, 3>(Xh, Xl, ph, pl, Wh, Wl,
                           O, nullptr, nullptr, nullptr, nullptr, 0,
                           DCc, Dc, DCc, Dc, nullptr, nullptr, bias);
}

// ---------------- conversion kernels ------------------------------------------
// batched P+S split: grid.y selects tensor
__global__ void k_split2(const float* __restrict__ X0, __half* __restrict__ H0, __half* __restrict__ L0,
                         const float* __restrict__ X1, __half* __restrict__ H1, __half* __restrict__ L1,
                         int n) {
    const float* X = blockIdx.y ? X1 : X0;
    __half* H = blockIdx.y ? H1 : H0;
    __half* L = blockIdx.y ? L1 : L0;
    int i = (blockIdx.x * blockDim.x + threadIdx.x) * 4;
    if (i >= n) return;
    float4 v = *(const float4*)(X + i);
    __half h0, h1, h2, h3, l0, l1, l2, l3;
    split2(v.x, h0, l0); split2(v.y, h1, l1);
    split2(v.z, h2, l2); split2(v.w, h3, l3);
    *(__half2*)(H + i)     = __halves2half2(h0, h1);
    *(__half2*)(H + i + 2) = __halves2half2(h2, h3);
    *(__half2*)(L + i)     = __halves2half2(l0, l1);
    *(__half2*)(L + i + 2) = __halves2half2(l2, l3);
}

// transpose + split: X[z][R][C] f32 -> H/L [z][C][R] fp16
__global__ void k_splitT(const float* __restrict__ X,
                         __half* __restrict__ H, __half* __restrict__ L,
                         int R, int C) {
    __shared__ float t[32][33];
    int z = blockIdx.z;
    int x0 = blockIdx.x * 32;
    int y0 = blockIdx.y * 32;
    const float* Xz = X + (size_t)z * R * C;
    #pragma unroll
    for (int i = 0; i < 4; i++) {
        int r = y0 + threadIdx.y * 4 + i;
        t[threadIdx.y * 4 + i][threadIdx.x] = Xz[(size_t)r * C + x0 + threadIdx.x];
    }
    __syncthreads();
    size_t zb = (size_t)z * R * C;
    #pragma unroll
    for (int i = 0; i < 4; i++) {
        int oc = x0 + threadIdx.y * 4 + i;
        float v = t[threadIdx.x][threadIdx.y * 4 + i];
        __half h, l;
        split2(v, h, l);
        H[zb + (size_t)oc * R + y0 + threadIdx.x] = h;
        L[zb + (size_t)oc * R + y0 + threadIdx.x] = l;
    }
}

// all 4 projection/FFN weights in one guarded launch.
// z: 0=Wp(R=Dc,C=INNER) 1=Ws(same) 2=Wfp(R=DCc,C=Dc) 3=Wfs(same)
__global__ void k_splitT4(const float* __restrict__ Wp,  __half* __restrict__ WpH,  __half* __restrict__ WpL,
                          const float* __restrict__ Ws,  __half* __restrict__ WsH,  __half* __restrict__ WsL,
                          const float* __restrict__ Wfp, __half* __restrict__ WfpH, __half* __restrict__ WfpL,
                          const float* __restrict__ Wfs, __half* __restrict__ WfsH, __half* __restrict__ WfsL) {
    __shared__ float t[32][33];
    int z = blockIdx.z;
    int R = (z < 2) ? Dc : DCc;
    int C = (z < 2) ? INNERc : Dc;
    if ((int)blockIdx.x * 32 >= C || (int)blockIdx.y * 32 >= R) return;
    const float* X = (z == 0) ? Wp : (z == 1) ? Ws : (z == 2) ? Wfp : Wfs;
    __half* H = (z == 0) ? WpH : (z == 1) ? WsH : (z == 2) ? WfpH : WfsH;
    __half* L = (z == 0) ? WpL : (z == 1) ? WsL : (z == 2) ? WfpL : WfsL;
    int x0 = blockIdx.x * 32;
    int y0 = blockIdx.y * 32;
    #pragma unroll
    for (int i = 0; i < 4; i++) {
        int r = y0 + threadIdx.y * 4 + i;
        t[threadIdx.y * 4 + i][threadIdx.x] = X[(size_t)r * C + x0 + threadIdx.x];
    }
    __syncthreads();
    #pragma unroll
    for (int i = 0; i < 4; i++) {
        int oc = x0 + threadIdx.y * 4 + i;
        float v = t[threadIdx.x][threadIdx.y * 4 + i];
        __half h, l;
        split2(v, h, l);
        H[(size_t)oc * R + y0 + threadIdx.x] = h;
        L[(size_t)oc * R + y0 + threadIdx.x] = l;
    }
}

// ---------------- merged pools -------------------------------------------------
__global__ void k_pool2() {
    int idx = blockIdx.x * blockDim.x + threadIdx.x;
    const int tot = Bc * L2c * HDc;
    if (idx >= tot) return;
    int b = idx / (L2c * HDc);
    int r = idx - b * (L2c * HDc);
    if (blockIdx.y == 0) {
        float m = g_wp[((size_t)b * Hc) * L2c * HDc + r];
        #pragma unroll
        for (int h = 1; h < Hc; h++)
            m = fmaxf(m, g_wp[((size_t)(b * Hc + h)) * L2c * HDc + r]);
        __half hh, ll;
        split2(m, hh, ll);
        g_poolph[idx] = hh;
        g_poolpl[idx] = ll;
    } else {
        float m = g_ws[((size_t)b * Hc) * L1c * HDc + r];
        #pragma unroll
        for (int h = 1; h < Hc; h++)
            m = fmaxf(m, g_ws[((size_t)(b * Hc + h)) * L1c * HDc + r]);
        __half hh, ll;
        split2(m, hh, ll);
        g_poolsh[idx] = hh;
        g_poolsl[idx] = ll;
    }
}

// ---------------- launcher -----------------------------------------------------
template<typename T>
static T* sym_addr(const void* sym) {
    void* p = nullptr;
    cudaGetSymbolAddress(&p, sym);
    return (T*)p;
}

extern "C" void kernel_launch(void* const* d_in, const int* in_sizes, int n_in,
                              void* d_out, int out_size) {
    const float* P    = (const float*)d_in[0];
    const float* S    = (const float*)d_in[1];
    const float* pm   = (const float*)d_in[2];
    const float* sm   = (const float*)d_in[3];
    const float* Waff = (const float*)d_in[4];
    const float* Wp   = (const float*)d_in[5];
    const float* Ws   = (const float*)d_in[6];
    const float* Wfp  = (const float*)d_in[7];
    const float* bfp  = (const float*)d_in[8];
    const float* Wfs  = (const float*)d_in[9];
    const float* bfs  = (const float*)d_in[10];

    float* outp = (float*)d_out;
    float* outs = outp + (size_t)Bc * L1c * Dc;

    __half* Ph     = sym_addr<__half>(g_Ph);
    __half* Pl     = sym_addr<__half>(g_Pl);
    __half* Sh     = sym_addr<__half>(g_Sh);
    __half* Sl     = sym_addr<__half>(g_Sl);
    __half* WaffTh = sym_addr<__half>(g_WaffTh);
    __half* WaffTl = sym_addr<__half>(g_WaffTl);
    __half* WpTh   = sym_addr<__half>(g_WpTh);
    __half* WpTl   = sym_addr<__half>(g_WpTl);
    __half* WsTh   = sym_addr<__half>(g_WsTh);
    __half* WsTl   = sym_addr<__half>(g_WsTl);
    __half* WfpTh  = sym_addr<__half>(g_WfpTh);
    __half* WfpTl  = sym_addr<__half>(g_WfpTl);
    __half* WfsTh  = sym_addr<__half>(g_WfsTh);
    __half* WfsTl  = sym_addr<__half>(g_WfsTl);

    cudaFuncSetAttribute(k_pw,   cudaFuncAttributeMaxDynamicSharedMemorySize, SM_P3);
    cudaFuncSetAttribute(k_aff,  cudaFuncAttributeMaxDynamicSharedMemorySize, SM_P3);
    cudaFuncSetAttribute(k_proj, cudaFuncAttributeMaxDynamicSharedMemorySize, SM_P2);
    cudaFuncSetAttribute(k_wpws, cudaFuncAttributeMaxDynamicSharedMemorySize, SM_P2);
    cudaFuncSetAttribute(k_ffn,  cudaFuncAttributeMaxDynamicSharedMemorySize, SM_P2);

    // conversions — exactly 3 launches (ncu empirically captures launch #4 = k_pw)
    {
        int n = Bc * L1c * Dc;
        k_split2<<<dim3(n / 1024, 2), 256>>>(P, Ph, Pl, S, Sh, Sl, n);
    }
    k_splitT<<<dim3(Dc / 32, Dc / 32, Hc), dim3(32, 8)>>>(Waff, WaffTh, WaffTl, Dc, Dc);
    k_splitT4<<<dim3(INNERc / 32, DCc / 32, 4), dim3(32, 8)>>>(
        Wp, WpTh, WpTl, Ws, WsTh, WsTl, Wfp, WfpTh, WfpTl, Wfs, WfsTh, WfsTl);

    dim3 blk(256);

    k_pw  <<<dim3(4, 4, Bc * Hc), blk, SM_P3>>>();
    k_aff <<<dim3(4, 4, Bc * Hc), blk, SM_P3>>>(pm, sm);
    k_proj<<<dim3(4, 8, Bc * 2),  blk, SM_P2>>>();
    k_wpws<<<dim3(1, 4, Bc * Hc * 2), blk, SM_P2>>>();

    { int tot = Bc * L2c * HDc; k_pool2<<<dim3((tot + 255) / 256, 2), 256>>>(); }

    k_ffn <<<dim3(4, 4, Bc * 2), blk, SM_P2>>>(bfp, bfs, outp, outs);
}